// round 11
// baseline (speedup 1.0000x reference)
#include <cuda_runtime.h>
#include <cuda_fp16.h>
#include <math.h>
#include <stdint.h>

#define NN 50000
#define NE 800000
#define NG 1024
#define NP 16384
#define NC 16
#define INCH 64
#define EMB 128
#define HID 256
#define BUCKET_SLOTS ((NP / 32 + NC) * 32)   // 16896
#define REG_BLOCKS (NP / 32 + NC)            // 528

// ---------------- scratch ----------------
__device__ float  g_dinv[NN];
__device__ int    g_icnt[NN];
__device__ int    g_rowptr[NN + 1];
__device__ int    g_cursor_node[NN];
__device__ int    g_csr[NE];
__device__ __half g_xh[NN * INCH];       // fp16 copy of x
__device__ __half g_hws[NN * EMB];       // fp16 dinv*relu(h1)
__device__ float  g_gsum[NG * EMB];
__device__ float  g_ge[NG * EMB];
__device__ int    g_bucket[BUCKET_SLOTS];

// ---------------- helpers ----------------
__device__ __forceinline__ void red_add_v2(float* addr, float a, float b) {
    asm volatile("red.global.add.v2.f32 [%0], {%1, %2};"
                 :: "l"(addr), "f"(a), "f"(b) : "memory");
}
__device__ __forceinline__ float4 f4add(float4 a, float4 b) {
    return make_float4(a.x + b.x, a.y + b.y, a.z + b.z, a.w + b.w);
}
__device__ __forceinline__ uint32_t cvt_tf32(float f) {
    uint32_t u;
    asm("cvt.rna.tf32.f32 %0, %1;" : "=r"(u) : "f"(f));
    return u;
}
__device__ __forceinline__ void mma_tf32(float* d, const uint32_t* a,
                                         uint32_t b0, uint32_t b1) {
    asm("mma.sync.aligned.m16n8k8.row.col.f32.tf32.tf32.f32 "
        "{%0,%1,%2,%3}, {%4,%5,%6,%7}, {%8,%9}, {%0,%1,%2,%3};"
        : "+f"(d[0]), "+f"(d[1]), "+f"(d[2]), "+f"(d[3])
        : "r"(a[0]), "r"(a[1]), "r"(a[2]), "r"(a[3]), "r"(b0), "r"(b1));
}
// load 4 consecutive halves as float4 (8-byte load)
__device__ __forceinline__ float4 ldh4(const __half* p) {
    uint2 u = *(const uint2*)p;
    __half2 h0 = *(__half2*)&u.x, h1 = *(__half2*)&u.y;
    float2 f0 = __half22float2(h0), f1 = __half22float2(h1);
    return make_float4(f0.x, f0.y, f1.x, f1.y);
}

// ---------------- x -> fp16, plus zeroing of g_icnt and g_gsum ----------------
__global__ void k_tohalf(const float* __restrict__ x) {
    int i = blockIdx.x * blockDim.x + threadIdx.x;
    if (i < NN * INCH / 4) {
        float4 v = ((const float4*)x)[i];
        __half2 h0 = __floats2half2_rn(v.x, v.y);
        __half2 h1 = __floats2half2_rn(v.z, v.w);
        ((uint2*)g_xh)[i] = make_uint2(*(uint32_t*)&h0, *(uint32_t*)&h1);
    }
    if (i < NN / 4 + 1) {
        if (i * 4 + 3 < NN) ((int4*)g_icnt)[i] = make_int4(0, 0, 0, 0);
        else for (int j = i * 4; j < NN; j++) g_icnt[j] = 0;
    }
    if (i < NG * EMB / 4)
        ((float4*)g_gsum)[i] = make_float4(0.f, 0.f, 0.f, 0.f);
}

// ---------------- degree histogram (4 edges per thread) ----------------
__global__ void k_icnt(const int* __restrict__ ei) {
    int i = blockIdx.x * blockDim.x + threadIdx.x;
    if (i < NE / 4) {
        int4 t = ((const int4*)(ei + NE))[i];
        atomicAdd(&g_icnt[t.x], 1);
        atomicAdd(&g_icnt[t.y], 1);
        atomicAdd(&g_icnt[t.z], 1);
        atomicAdd(&g_icnt[t.w], 1);
    }
}

// ---------------- single-block two-pass scan (+ dinv + cursor init) ----------------
__global__ void __launch_bounds__(1024) k_scanA() {
    __shared__ int wsum[32];
    const int IT = (NN + 1023) / 1024;   // 49
    int t = threadIdx.x;
    int lane = t & 31, w = t >> 5;
    int base = t * IT;

    int s = 0;
    for (int i = 0; i < IT; i++) {
        int idx = base + i;
        if (idx < NN) s += g_icnt[idx];
    }
    int v = s;
#pragma unroll
    for (int o = 1; o < 32; o <<= 1) {
        int u = __shfl_up_sync(0xffffffffu, v, o);
        if (lane >= o) v += u;
    }
    if (lane == 31) wsum[w] = v;
    __syncthreads();
    if (w == 0) {
        int ws = wsum[lane];
#pragma unroll
        for (int o = 1; o < 32; o <<= 1) {
            int u = __shfl_up_sync(0xffffffffu, ws, o);
            if (lane >= o) ws += u;
        }
        wsum[lane] = ws;
    }
    __syncthreads();
    int run = (v - s) + (w > 0 ? wsum[w - 1] : 0);

    for (int i = 0; i < IT; i++) {
        int idx = base + i;
        if (idx < NN) {
            int c = g_icnt[idx];
            g_rowptr[idx] = run;
            g_cursor_node[idx] = run;
            g_dinv[idx] = rsqrtf((float)(c + 1));
            run += c;
        }
    }
    if (t == 1023) g_rowptr[NN] = NE;
}

__global__ void k_fill(const int* __restrict__ ei) {
    int i = blockIdx.x * blockDim.x + threadIdx.x;
    if (i < NE / 4) {
        int4 c = ((const int4*)(ei + NE))[i];
        int4 r = ((const int4*)ei)[i];
        g_csr[atomicAdd(&g_cursor_node[c.x], 1)] = r.x;
        g_csr[atomicAdd(&g_cursor_node[c.y], 1)] = r.y;
        g_csr[atomicAdd(&g_cursor_node[c.z], 1)] = r.z;
        g_csr[atomicAdd(&g_cursor_node[c.w], 1)] = r.w;
    }
}

// ---------------- fused gather(fp16) + tf32 GEMM, layer 1 (K=64) ----------------
// gather: half-warp per node (16 lanes x 4 halves = 64 cols)  [R9 structure]
__global__ void __launch_bounds__(256) k_gcn1(
    const float* __restrict__ W, const float* __restrict__ bias)
{
    constexpr int K = 64, KP = 68, BM = 64;
    __shared__ uint32_t sXu[BM * KP];

    int tid = threadIdx.x;
    int warp = tid >> 5, lane = tid & 31;
    int row0 = blockIdx.x * BM;

    int half = lane >> 4, l = lane & 15;
    for (int it = 0; it < 4; it++) {
        int nl = warp * 8 + it * 2 + half;
        int node = row0 + nl;
        float4 acc = make_float4(0.f, 0.f, 0.f, 0.f);
        if (node < NN) {
            float dn = g_dinv[node];
            acc = ldh4(&g_xh[node * INCH + l * 4]);
            acc.x *= dn; acc.y *= dn; acc.z *= dn; acc.w *= dn;
            int e = g_rowptr[node], end = g_rowptr[node + 1];
            for (; e + 4 <= end; e += 4) {
                int s0 = g_csr[e], s1 = g_csr[e + 1], s2 = g_csr[e + 2], s3 = g_csr[e + 3];
                float4 a0 = ldh4(&g_xh[s0 * INCH + l * 4]);
                float4 a1 = ldh4(&g_xh[s1 * INCH + l * 4]);
                float4 a2 = ldh4(&g_xh[s2 * INCH + l * 4]);
                float4 a3 = ldh4(&g_xh[s3 * INCH + l * 4]);
                float d0 = g_dinv[s0], d1 = g_dinv[s1], d2 = g_dinv[s2], d3 = g_dinv[s3];
                acc.x = fmaf(d0, a0.x, fmaf(d1, a1.x, fmaf(d2, a2.x, fmaf(d3, a3.x, acc.x))));
                acc.y = fmaf(d0, a0.y, fmaf(d1, a1.y, fmaf(d2, a2.y, fmaf(d3, a3.y, acc.y))));
                acc.z = fmaf(d0, a0.z, fmaf(d1, a1.z, fmaf(d2, a2.z, fmaf(d3, a3.z, acc.z))));
                acc.w = fmaf(d0, a0.w, fmaf(d1, a1.w, fmaf(d2, a2.w, fmaf(d3, a3.w, acc.w))));
            }
            for (; e < end; e++) {
                int s = g_csr[e];
                float4 a = ldh4(&g_xh[s * INCH + l * 4]);
                float ds = g_dinv[s];
                acc.x = fmaf(ds, a.x, acc.x);
                acc.y = fmaf(ds, a.y, acc.y);
                acc.z = fmaf(ds, a.z, acc.z);
                acc.w = fmaf(ds, a.w, acc.w);
            }
            acc.x *= dn; acc.y *= dn; acc.z *= dn; acc.w *= dn;  // left norm
        }
        uint4 uv = make_uint4(cvt_tf32(acc.x), cvt_tf32(acc.y),
                              cvt_tf32(acc.z), cvt_tf32(acc.w));
        *(uint4*)&sXu[nl * KP + l * 4] = uv;
    }
    __syncthreads();

    // tf32 GEMM
    int mt = warp & 3, nh = warp >> 2;
    int ra = lane >> 2, ca = lane & 3;
    float d[8][4];
#pragma unroll
    for (int nt = 0; nt < 8; nt++)
        d[nt][0] = d[nt][1] = d[nt][2] = d[nt][3] = 0.f;

#pragma unroll
    for (int k0 = 0; k0 < K; k0 += 8) {
        const uint32_t* pa = &sXu[(mt * 16 + ra) * KP + k0 + ca];
        uint32_t A[4] = { pa[0], pa[8 * KP], pa[4], pa[8 * KP + 4] };
        const float* wb = &W[(k0 + ca) * 128 + nh * 64 + ra];
#pragma unroll
        for (int nt = 0; nt < 8; nt++) {
            uint32_t b0 = cvt_tf32(__ldg(wb + nt * 8));
            uint32_t b1 = cvt_tf32(__ldg(wb + 4 * 128 + nt * 8));
            mma_tf32(d[nt], A, b0, b1);
        }
    }

    // epilogue: bias + relu + dinv -> g_hws (fp16)
    int gr0 = row0 + mt * 16 + ra;
    int gr1 = gr0 + 8;
    float dv0 = (gr0 < NN) ? g_dinv[gr0] : 0.f;
    float dv1 = (gr1 < NN) ? g_dinv[gr1] : 0.f;
#pragma unroll
    for (int nt = 0; nt < 8; nt++) {
        int col = nh * 64 + nt * 8 + 2 * ca;
        float bx = __ldg(&bias[col]), by = __ldg(&bias[col + 1]);
        if (gr0 < NN) {
            __half2 o = __floats2half2_rn(fmaxf(d[nt][0] + bx, 0.f) * dv0,
                                          fmaxf(d[nt][1] + by, 0.f) * dv0);
            *(__half2*)&g_hws[gr0 * EMB + col] = o;
        }
        if (gr1 < NN) {
            __half2 o = __floats2half2_rn(fmaxf(d[nt][2] + bx, 0.f) * dv1,
                                          fmaxf(d[nt][3] + by, 0.f) * dv1);
            *(__half2*)&g_hws[gr1 * EMB + col] = o;
        }
    }
}

// ---------------- fused gather(fp16) + tf32 GEMM + pool, layer 2 (K=128) ----------------
// gather: warp per node (32 lanes x 4 halves = 128 cols)  [R9 structure]
__global__ void __launch_bounds__(256) k_gcn2(
    const float* __restrict__ W, const float* __restrict__ bias,
    const int* __restrict__ batch)
{
    constexpr int K = 128, KP = 132, BM = 64;
    __shared__ uint32_t sXu[BM * KP];

    int tid = threadIdx.x;
    int warp = tid >> 5, lane = tid & 31;
    int row0 = blockIdx.x * BM;

    for (int it = 0; it < 8; it++) {
        int nl = warp * 8 + it;
        int node = row0 + nl;
        float4 acc = make_float4(0.f, 0.f, 0.f, 0.f);
        if (node < NN) {
            acc = ldh4(&g_hws[node * EMB + lane * 4]);  // self
            int e = g_rowptr[node], end = g_rowptr[node + 1];
            for (; e + 4 <= end; e += 4) {
                int s0 = g_csr[e], s1 = g_csr[e + 1], s2 = g_csr[e + 2], s3 = g_csr[e + 3];
                float4 a0 = ldh4(&g_hws[s0 * EMB + lane * 4]);
                float4 a1 = ldh4(&g_hws[s1 * EMB + lane * 4]);
                float4 a2 = ldh4(&g_hws[s2 * EMB + lane * 4]);
                float4 a3 = ldh4(&g_hws[s3 * EMB + lane * 4]);
                acc = f4add(acc, f4add(f4add(a0, a1), f4add(a2, a3)));
            }
            for (; e < end; e++) {
                int s = g_csr[e];
                acc = f4add(acc, ldh4(&g_hws[s * EMB + lane * 4]));
            }
            float dn = g_dinv[node];
            acc.x *= dn; acc.y *= dn; acc.z *= dn; acc.w *= dn;
        }
        uint4 uv = make_uint4(cvt_tf32(acc.x), cvt_tf32(acc.y),
                              cvt_tf32(acc.z), cvt_tf32(acc.w));
        *(uint4*)&sXu[nl * KP + lane * 4] = uv;
    }
    __syncthreads();

    // tf32 GEMM
    int mt = warp & 3, nh = warp >> 2;
    int ra = lane >> 2, ca = lane & 3;
    float d[8][4];
#pragma unroll
    for (int nt = 0; nt < 8; nt++)
        d[nt][0] = d[nt][1] = d[nt][2] = d[nt][3] = 0.f;

#pragma unroll 4
    for (int k0 = 0; k0 < K; k0 += 8) {
        const uint32_t* pa = &sXu[(mt * 16 + ra) * KP + k0 + ca];
        uint32_t A[4] = { pa[0], pa[8 * KP], pa[4], pa[8 * KP + 4] };
        const float* wb = &W[(k0 + ca) * 128 + nh * 64 + ra];
#pragma unroll
        for (int nt = 0; nt < 8; nt++) {
            uint32_t b0 = cvt_tf32(__ldg(wb + nt * 8));
            uint32_t b1 = cvt_tf32(__ldg(wb + 4 * 128 + nt * 8));
            mma_tf32(d[nt], A, b0, b1);
        }
    }

    // epilogue: bias + relu + pooled red.add into g_gsum
    int gr0 = row0 + mt * 16 + ra;
    int gr1 = gr0 + 8;
    int b0i = (gr0 < NN) ? batch[gr0] : 0;
    int b1i = (gr1 < NN) ? batch[gr1] : 0;
#pragma unroll
    for (int nt = 0; nt < 8; nt++) {
        int col = nh * 64 + nt * 8 + 2 * ca;
        float bx = __ldg(&bias[col]), by = __ldg(&bias[col + 1]);
        if (gr0 < NN)
            red_add_v2(&g_gsum[b0i * EMB + col],
                       fmaxf(d[nt][0] + bx, 0.f), fmaxf(d[nt][1] + by, 0.f));
        if (gr1 < NN)
            red_add_v2(&g_gsum[b1i * EMB + col],
                       fmaxf(d[nt][2] + bx, 0.f), fmaxf(d[nt][3] + by, 0.f));
    }
}

// ---------------- mean epilogue ----------------
__global__ void __launch_bounds__(256) k_ge(const int* __restrict__ batch) {
    int w = (blockIdx.x * 256 + threadIdx.x) >> 5;
    int lane = threadIdx.x & 31;
    if (w >= NG) return;
    int cnt = 0;
    if (lane == 0) {
        int lo = 0, hi = NN;
        while (lo < hi) { int m = (lo + hi) >> 1; if (batch[m] < w) lo = m + 1; else hi = m; }
        int a = lo;
        hi = NN;
        while (lo < hi) { int m = (lo + hi) >> 1; if (batch[m] < w + 1) lo = m + 1; else hi = m; }
        cnt = lo - a;
    }
    cnt = __shfl_sync(0xffffffffu, cnt, 0);
    float inv = 1.0f / fmaxf((float)cnt, 1.0f);
    float4 v = *(const float4*)&g_gsum[w * EMB + lane * 4];
    v.x *= inv; v.y *= inv; v.z *= inv; v.w *= inv;
    *(float4*)&g_ge[w * EMB + lane * 4] = v;
}

// ---------------- fused bucketing ----------------
__global__ void __launch_bounds__(1024) k_bucket(const int* __restrict__ ecl) {
    __shared__ int s_cnt[NC];
    __shared__ int s_start[NC];
    __shared__ int s_cur[NC];
    int t = threadIdx.x;
    if (t < NC) s_cnt[t] = 0;
    __syncthreads();
    for (int p = t; p < NP; p += 1024) atomicAdd(&s_cnt[ecl[p]], 1);
    __syncthreads();
    if (t == 0) {
        int a = 0;
        for (int c = 0; c < NC; c++) {
            s_start[c] = a;
            a += ((s_cnt[c] + 31) / 32) * 32;
        }
    }
    __syncthreads();
    for (int i = t; i < BUCKET_SLOTS; i += 1024) g_bucket[i] = -1;
    if (t < NC) s_cur[t] = s_start[t];
    __syncthreads();
    for (int p = t; p < NP; p += 1024) {
        int c = ecl[p];
        int pos = atomicAdd(&s_cur[c], 1);
        g_bucket[pos] = p;
    }
}

// ---------------- tf32 tensor-core regressor: 32 pairs per block ----------------
__global__ void __launch_bounds__(256) k_reg(
    const int* __restrict__ ddb, const int* __restrict__ ecl,
    const float* __restrict__ w1, const float* __restrict__ b1,
    const float* __restrict__ w2, const float* __restrict__ b2,
    float* __restrict__ out)
{
    __shared__ int      s_pid[32];
    __shared__ uint32_t s_pairU[32 * 268];
    __shared__ float    s_b1[HID];
    __shared__ float    s_w2[HID];
    __shared__ float    s_out[32];

    int tid = threadIdx.x;
    int warp = tid >> 5, lane = tid & 31;
    int base = blockIdx.x * 32;
    if (tid < 32) { s_pid[tid] = g_bucket[base + tid]; s_out[tid] = 0.f; }
    __syncthreads();

    int c = -1;
    for (int s = 0; s < 32 && c < 0; s++) {
        int p = s_pid[s];
        if (p >= 0) c = ecl[p];
    }
    if (c < 0) return;

    s_b1[tid] = b1[c * HID + tid];
    s_w2[tid] = w2[c * HID + tid];

    for (int i = tid; i < 32 * HID; i += 256) {
        int s = i >> 8, j = i & 255;
        int p = s_pid[s];
        float v = 0.0f;
        if (p >= 0) {
            int q = (j < 128) ? ddb[p] : ddb[NP + p];
            v = g_ge[q * EMB + (j & 127)];
        }
        s_pairU[s * 268 + j] = cvt_tf32(v);
    }
    __syncthreads();

    const float* Wc = w1 + c * (HID * HID);
    int n0 = warp * 32;
    int ra = lane >> 2, ca = lane & 3;

    float d[2][4][4];
#pragma unroll
    for (int mt = 0; mt < 2; mt++)
#pragma unroll
        for (int nt = 0; nt < 4; nt++)
            d[mt][nt][0] = d[mt][nt][1] = d[mt][nt][2] = d[mt][nt][3] = 0.f;

    for (int k0 = 0; k0 < HID; k0 += 8) {
        const uint32_t* pr = &s_pairU[ra * 268 + k0 + ca];
        uint32_t A[2][4];
        A[0][0] = pr[0];
        A[0][1] = pr[8 * 268];
        A[0][2] = pr[4];
        A[0][3] = pr[8 * 268 + 4];
        A[1][0] = pr[16 * 268];
        A[1][1] = pr[24 * 268];
        A[1][2] = pr[16 * 268 + 4];
        A[1][3] = pr[24 * 268 + 4];
        const float* wp0 = Wc + (k0 + ca) * HID + n0 + ra;
        const float* wp1 = wp0 + 4 * HID;
#pragma unroll
        for (int nt = 0; nt < 4; nt++) {
            uint32_t b0 = cvt_tf32(__ldg(wp0 + nt * 8));
            uint32_t b1v = cvt_tf32(__ldg(wp1 + nt * 8));
            mma_tf32(d[0][nt], A[0], b0, b1v);
            mma_tf32(d[1][nt], A[1], b0, b1v);
        }
    }

    float rowsum[2][2] = {{0.f, 0.f}, {0.f, 0.f}};
#pragma unroll
    for (int mt = 0; mt < 2; mt++) {
#pragma unroll
        for (int nt = 0; nt < 4; nt++) {
            int colb = n0 + nt * 8 + 2 * ca;
            float b1a = s_b1[colb],     w2a = s_w2[colb];
            float b1b = s_b1[colb + 1], w2b = s_w2[colb + 1];
            rowsum[mt][0] += fmaxf(d[mt][nt][0] + b1a, 0.f) * w2a
                           + fmaxf(d[mt][nt][1] + b1b, 0.f) * w2b;
            rowsum[mt][1] += fmaxf(d[mt][nt][2] + b1a, 0.f) * w2a
                           + fmaxf(d[mt][nt][3] + b1b, 0.f) * w2b;
        }
    }
#pragma unroll
    for (int mt = 0; mt < 2; mt++)
#pragma unroll
        for (int hi = 0; hi < 2; hi++) {
            float v = rowsum[mt][hi];
            v += __shfl_xor_sync(0xffffffffu, v, 1);
            v += __shfl_xor_sync(0xffffffffu, v, 2);
            if (ca == 0) atomicAdd(&s_out[mt * 16 + hi * 8 + ra], v);
        }
    __syncthreads();

    if (tid < 32) {
        int p = s_pid[tid];
        if (p >= 0) out[p] = s_out[tid] + b2[c];
    }
}

// ---------------- host launch ----------------
extern "C" void kernel_launch(void* const* d_in, const int* in_sizes, int n_in,
                              void* d_out, int out_size)
{
    const float* x    = (const float*)d_in[0];
    const float* c1w  = (const float*)d_in[1];
    const float* c1b  = (const float*)d_in[2];
    const float* c2w  = (const float*)d_in[3];
    const float* c2b  = (const float*)d_in[4];
    const float* rw1  = (const float*)d_in[5];
    const float* rb1  = (const float*)d_in[6];
    const float* rw2  = (const float*)d_in[7];
    const float* rb2  = (const float*)d_in[8];
    const int*   ei   = (const int*)d_in[9];
    const int*   bat  = (const int*)d_in[10];
    const int*   ddb  = (const int*)d_in[11];
    const int*   ecl  = (const int*)d_in[12];
    float* out = (float*)d_out;

    const int T = 256;

    // 1: x->fp16 + zero icnt/gsum
    k_tohalf<<<(NN * INCH / 4 + T - 1) / T, T>>>(x);
    // 2-4: CSR build
    k_icnt<<<(NE / 4 + T - 1) / T, T>>>(ei);
    k_scanA<<<1, 1024>>>();
    k_fill<<<(NE / 4 + T - 1) / T, T>>>(ei);
    // 5: layer 1
    k_gcn1<<<(NN + 63) / 64, T>>>(c1w, c1b);
    // 6: layer 2
    k_gcn2<<<(NN + 63) / 64, T>>>(c2w, c2b, bat);
    // 7: mean
    k_ge<<<(NG * 32 + T - 1) / T, T>>>(bat);
    // 8-9: bucketing + regressor
    k_bucket<<<1, 1024>>>(ecl);
    k_reg<<<REG_BLOCKS, T>>>(ddb, ecl, rw1, rb1, rw2, rb2, out);
}

// round 12
// speedup vs baseline: 1.4749x; 1.4749x over previous
#include <cuda_runtime.h>
#include <cuda_fp16.h>
#include <math.h>
#include <stdint.h>

#define NN 50000
#define NE 800000
#define NG 1024
#define NP 16384
#define NC 16
#define INCH 64
#define EMB 128
#define HID 256
#define BUCKET_SLOTS ((NP / 32 + NC) * 32)   // 16896
#define REG_BLOCKS (NP / 32 + NC)            // 528
#define NPB 128
#define NBLK ((NN + NPB - 1) / NPB)           // 391

// ---------------- scratch ----------------
__device__ float  g_dinv[NN];
__device__ int    g_icnt[NN];
__device__ int    g_rowptr[NN + 1];
__device__ int    g_cursor_node[NN];
__device__ int    g_bsum[512];
__device__ int    g_csr[NE];
__device__ __half g_xh[NN * INCH];       // fp16 copy of x
__device__ __half g_hws[NN * EMB];       // fp16 dinv*relu(h1)
__device__ float  g_gsum[NG * EMB];
__device__ float  g_ge[NG * EMB];
__device__ int    g_bucket[BUCKET_SLOTS];

// ---------------- helpers ----------------
__device__ __forceinline__ void red_add_v2(float* addr, float a, float b) {
    asm volatile("red.global.add.v2.f32 [%0], {%1, %2};"
                 :: "l"(addr), "f"(a), "f"(b) : "memory");
}
__device__ __forceinline__ float4 f4add(float4 a, float4 b) {
    return make_float4(a.x + b.x, a.y + b.y, a.z + b.z, a.w + b.w);
}
__device__ __forceinline__ uint32_t cvt_tf32(float f) {
    uint32_t u;
    asm("cvt.rna.tf32.f32 %0, %1;" : "=r"(u) : "f"(f));
    return u;
}
__device__ __forceinline__ void mma_tf32(float* d, const uint32_t* a,
                                         uint32_t b0, uint32_t b1) {
    asm("mma.sync.aligned.m16n8k8.row.col.f32.tf32.tf32.f32 "
        "{%0,%1,%2,%3}, {%4,%5,%6,%7}, {%8,%9}, {%0,%1,%2,%3};"
        : "+f"(d[0]), "+f"(d[1]), "+f"(d[2]), "+f"(d[3])
        : "r"(a[0]), "r"(a[1]), "r"(a[2]), "r"(a[3]), "r"(b0), "r"(b1));
}
// load 4 consecutive halves as float4 (8-byte load)
__device__ __forceinline__ float4 ldh4(const __half* p) {
    uint2 u = *(const uint2*)p;
    __half2 h0 = *(__half2*)&u.x, h1 = *(__half2*)&u.y;
    float2 f0 = __half22float2(h0), f1 = __half22float2(h1);
    return make_float4(f0.x, f0.y, f1.x, f1.y);
}

// ---------------- x -> fp16 ----------------
__global__ void k_tohalf(const float* __restrict__ x) {
    int i = blockIdx.x * blockDim.x + threadIdx.x;
    if (i < NN * INCH / 4) {
        float4 v = ((const float4*)x)[i];
        __half2 h0 = __floats2half2_rn(v.x, v.y);
        __half2 h1 = __floats2half2_rn(v.z, v.w);
        uint2 u = make_uint2(*(uint32_t*)&h0, *(uint32_t*)&h1);
        ((uint2*)g_xh)[i] = u;
    }
}

// ---------------- degree histogram (4 edges per thread) ----------------
__global__ void k_icnt(const int* __restrict__ ei) {
    int i = blockIdx.x * blockDim.x + threadIdx.x;
    if (i < NE / 4) {
        int4 t = ((const int4*)(ei + NE))[i];
        atomicAdd(&g_icnt[t.x], 1);
        atomicAdd(&g_icnt[t.y], 1);
        atomicAdd(&g_icnt[t.z], 1);
        atomicAdd(&g_icnt[t.w], 1);
    }
}

// ---------------- prefix scan (+ fused dinv) ----------------
__global__ void k_scan1() {
    __shared__ int sm[NPB];
    int i = blockIdx.x * NPB + threadIdx.x;
    int v = (i < NN) ? g_icnt[i] : 0;
    if (i < NN) g_dinv[i] = rsqrtf((float)(v + 1));
    sm[threadIdx.x] = v;
    __syncthreads();
    for (int s = NPB / 2; s > 0; s >>= 1) {
        if (threadIdx.x < s) sm[threadIdx.x] += sm[threadIdx.x + s];
        __syncthreads();
    }
    if (threadIdx.x == 0) g_bsum[blockIdx.x] = sm[0];
}
__global__ void k_scan2() {
    __shared__ int sm[512];
    int t = threadIdx.x;
    int v = (t < NBLK) ? g_bsum[t] : 0;
    sm[t] = v;
    __syncthreads();
    for (int s = 1; s < 512; s <<= 1) {
        int a = (t >= s) ? sm[t - s] : 0;
        __syncthreads();
        sm[t] += a;
        __syncthreads();
    }
    if (t < NBLK) g_bsum[t] = sm[t] - v;
}
__global__ void k_scan3() {
    __shared__ int sm[NPB];
    int t = threadIdx.x;
    int i = blockIdx.x * NPB + t;
    int v = (i < NN) ? g_icnt[i] : 0;
    sm[t] = v;
    __syncthreads();
    for (int s = 1; s < NPB; s <<= 1) {
        int a = (t >= s) ? sm[t - s] : 0;
        __syncthreads();
        sm[t] += a;
        __syncthreads();
    }
    if (i < NN) {
        int p = g_bsum[blockIdx.x] + sm[t] - v;
        g_rowptr[i] = p;
        g_cursor_node[i] = p;
        if (i == NN - 1) g_rowptr[NN] = NE;
    }
}
__global__ void k_fill(const int* __restrict__ ei) {
    int i = blockIdx.x * blockDim.x + threadIdx.x;
    if (i < NE / 4) {
        int4 c = ((const int4*)(ei + NE))[i];
        int4 r = ((const int4*)ei)[i];
        g_csr[atomicAdd(&g_cursor_node[c.x], 1)] = r.x;
        g_csr[atomicAdd(&g_cursor_node[c.y], 1)] = r.y;
        g_csr[atomicAdd(&g_cursor_node[c.z], 1)] = r.z;
        g_csr[atomicAdd(&g_cursor_node[c.w], 1)] = r.w;
    }
}

// ---------------- fused gather(fp16) + tf32 GEMM, layer 1 (K=64) ----------------
__global__ void __launch_bounds__(256) k_gcn1(
    const float* __restrict__ W, const float* __restrict__ bias)
{
    constexpr int K = 64, KP = 68, BM = 64;
    __shared__ uint32_t sXu[BM * KP];

    int tid = threadIdx.x;
    int warp = tid >> 5, lane = tid & 31;
    int row0 = blockIdx.x * BM;

    // gather phase: half-warp per node (16 lanes x 4 halves = 64 cols)
    int half = lane >> 4, l = lane & 15;
    for (int it = 0; it < 4; it++) {
        int nl = warp * 8 + it * 2 + half;
        int node = row0 + nl;
        float4 acc = make_float4(0.f, 0.f, 0.f, 0.f);
        if (node < NN) {
            float dn = g_dinv[node];
            acc = ldh4(&g_xh[node * INCH + l * 4]);
            acc.x *= dn; acc.y *= dn; acc.z *= dn; acc.w *= dn;
            int e = g_rowptr[node], end = g_rowptr[node + 1];
            for (; e + 4 <= end; e += 4) {
                int s0 = g_csr[e], s1 = g_csr[e + 1], s2 = g_csr[e + 2], s3 = g_csr[e + 3];
                float4 a0 = ldh4(&g_xh[s0 * INCH + l * 4]);
                float4 a1 = ldh4(&g_xh[s1 * INCH + l * 4]);
                float4 a2 = ldh4(&g_xh[s2 * INCH + l * 4]);
                float4 a3 = ldh4(&g_xh[s3 * INCH + l * 4]);
                float d0 = g_dinv[s0], d1 = g_dinv[s1], d2 = g_dinv[s2], d3 = g_dinv[s3];
                acc.x = fmaf(d0, a0.x, fmaf(d1, a1.x, fmaf(d2, a2.x, fmaf(d3, a3.x, acc.x))));
                acc.y = fmaf(d0, a0.y, fmaf(d1, a1.y, fmaf(d2, a2.y, fmaf(d3, a3.y, acc.y))));
                acc.z = fmaf(d0, a0.z, fmaf(d1, a1.z, fmaf(d2, a2.z, fmaf(d3, a3.z, acc.z))));
                acc.w = fmaf(d0, a0.w, fmaf(d1, a1.w, fmaf(d2, a2.w, fmaf(d3, a3.w, acc.w))));
            }
            for (; e < end; e++) {
                int s = g_csr[e];
                float4 a = ldh4(&g_xh[s * INCH + l * 4]);
                float ds = g_dinv[s];
                acc.x = fmaf(ds, a.x, acc.x);
                acc.y = fmaf(ds, a.y, acc.y);
                acc.z = fmaf(ds, a.z, acc.z);
                acc.w = fmaf(ds, a.w, acc.w);
            }
            acc.x *= dn; acc.y *= dn; acc.z *= dn; acc.w *= dn;  // left norm
        }
        uint4 uv = make_uint4(cvt_tf32(acc.x), cvt_tf32(acc.y),
                              cvt_tf32(acc.z), cvt_tf32(acc.w));
        *(uint4*)&sXu[nl * KP + l * 4] = uv;
    }
    __syncthreads();

    // tf32 GEMM
    int mt = warp & 3, nh = warp >> 2;
    int ra = lane >> 2, ca = lane & 3;
    float d[8][4];
#pragma unroll
    for (int nt = 0; nt < 8; nt++)
        d[nt][0] = d[nt][1] = d[nt][2] = d[nt][3] = 0.f;

#pragma unroll
    for (int k0 = 0; k0 < K; k0 += 8) {
        const uint32_t* pa = &sXu[(mt * 16 + ra) * KP + k0 + ca];
        uint32_t A[4] = { pa[0], pa[8 * KP], pa[4], pa[8 * KP + 4] };
        const float* wb = &W[(k0 + ca) * 128 + nh * 64 + ra];
#pragma unroll
        for (int nt = 0; nt < 8; nt++) {
            uint32_t b0 = cvt_tf32(__ldg(wb + nt * 8));
            uint32_t b1 = cvt_tf32(__ldg(wb + 4 * 128 + nt * 8));
            mma_tf32(d[nt], A, b0, b1);
        }
    }

    // epilogue: bias + relu + dinv -> g_hws (fp16)
    int gr0 = row0 + mt * 16 + ra;
    int gr1 = gr0 + 8;
    float dv0 = (gr0 < NN) ? g_dinv[gr0] : 0.f;
    float dv1 = (gr1 < NN) ? g_dinv[gr1] : 0.f;
#pragma unroll
    for (int nt = 0; nt < 8; nt++) {
        int col = nh * 64 + nt * 8 + 2 * ca;
        float bx = __ldg(&bias[col]), by = __ldg(&bias[col + 1]);
        if (gr0 < NN) {
            __half2 o = __floats2half2_rn(fmaxf(d[nt][0] + bx, 0.f) * dv0,
                                          fmaxf(d[nt][1] + by, 0.f) * dv0);
            *(__half2*)&g_hws[gr0 * EMB + col] = o;
        }
        if (gr1 < NN) {
            __half2 o = __floats2half2_rn(fmaxf(d[nt][2] + bx, 0.f) * dv1,
                                          fmaxf(d[nt][3] + by, 0.f) * dv1);
            *(__half2*)&g_hws[gr1 * EMB + col] = o;
        }
    }
}

// ---------------- fused gather(fp16) + tf32 GEMM + pool, layer 2 (K=128) ----------------
__global__ void __launch_bounds__(256) k_gcn2(
    const float* __restrict__ W, const float* __restrict__ bias,
    const int* __restrict__ batch)
{
    constexpr int K = 128, KP = 132, BM = 64;
    __shared__ uint32_t sXu[BM * KP];

    int tid = threadIdx.x;
    int warp = tid >> 5, lane = tid & 31;
    int row0 = blockIdx.x * BM;

    // gather phase: warp per node, lane handles 4 halves (8B loads)
    for (int it = 0; it < 8; it++) {
        int nl = warp * 8 + it;
        int node = row0 + nl;
        float4 acc = make_float4(0.f, 0.f, 0.f, 0.f);
        if (node < NN) {
            acc = ldh4(&g_hws[node * EMB + lane * 4]);  // self
            int e = g_rowptr[node], end = g_rowptr[node + 1];
            for (; e + 4 <= end; e += 4) {
                int s0 = g_csr[e], s1 = g_csr[e + 1], s2 = g_csr[e + 2], s3 = g_csr[e + 3];
                float4 a0 = ldh4(&g_hws[s0 * EMB + lane * 4]);
                float4 a1 = ldh4(&g_hws[s1 * EMB + lane * 4]);
                float4 a2 = ldh4(&g_hws[s2 * EMB + lane * 4]);
                float4 a3 = ldh4(&g_hws[s3 * EMB + lane * 4]);
                acc = f4add(acc, f4add(f4add(a0, a1), f4add(a2, a3)));
            }
            for (; e < end; e++) {
                int s = g_csr[e];
                acc = f4add(acc, ldh4(&g_hws[s * EMB + lane * 4]));
            }
            float dn = g_dinv[node];
            acc.x *= dn; acc.y *= dn; acc.z *= dn; acc.w *= dn;
        }
        uint4 uv = make_uint4(cvt_tf32(acc.x), cvt_tf32(acc.y),
                              cvt_tf32(acc.z), cvt_tf32(acc.w));
        *(uint4*)&sXu[nl * KP + lane * 4] = uv;
    }
    __syncthreads();

    // tf32 GEMM
    int mt = warp & 3, nh = warp >> 2;
    int ra = lane >> 2, ca = lane & 3;
    float d[8][4];
#pragma unroll
    for (int nt = 0; nt < 8; nt++)
        d[nt][0] = d[nt][1] = d[nt][2] = d[nt][3] = 0.f;

#pragma unroll 4
    for (int k0 = 0; k0 < K; k0 += 8) {
        const uint32_t* pa = &sXu[(mt * 16 + ra) * KP + k0 + ca];
        uint32_t A[4] = { pa[0], pa[8 * KP], pa[4], pa[8 * KP + 4] };
        const float* wb = &W[(k0 + ca) * 128 + nh * 64 + ra];
#pragma unroll
        for (int nt = 0; nt < 8; nt++) {
            uint32_t b0 = cvt_tf32(__ldg(wb + nt * 8));
            uint32_t b1 = cvt_tf32(__ldg(wb + 4 * 128 + nt * 8));
            mma_tf32(d[nt], A, b0, b1);
        }
    }

    // epilogue: bias + relu + pooled red.add into g_gsum
    int gr0 = row0 + mt * 16 + ra;
    int gr1 = gr0 + 8;
    int b0i = (gr0 < NN) ? batch[gr0] : 0;
    int b1i = (gr1 < NN) ? batch[gr1] : 0;
#pragma unroll
    for (int nt = 0; nt < 8; nt++) {
        int col = nh * 64 + nt * 8 + 2 * ca;
        float bx = __ldg(&bias[col]), by = __ldg(&bias[col + 1]);
        if (gr0 < NN)
            red_add_v2(&g_gsum[b0i * EMB + col],
                       fmaxf(d[nt][0] + bx, 0.f), fmaxf(d[nt][1] + by, 0.f));
        if (gr1 < NN)
            red_add_v2(&g_gsum[b1i * EMB + col],
                       fmaxf(d[nt][2] + bx, 0.f), fmaxf(d[nt][3] + by, 0.f));
    }
}

// ---------------- mean epilogue ----------------
__global__ void __launch_bounds__(256) k_ge(const int* __restrict__ batch) {
    int w = (blockIdx.x * 256 + threadIdx.x) >> 5;
    int lane = threadIdx.x & 31;
    if (w >= NG) return;
    int cnt = 0;
    if (lane == 0) {
        int lo = 0, hi = NN;
        while (lo < hi) { int m = (lo + hi) >> 1; if (batch[m] < w) lo = m + 1; else hi = m; }
        int a = lo;
        hi = NN;
        while (lo < hi) { int m = (lo + hi) >> 1; if (batch[m] < w + 1) lo = m + 1; else hi = m; }
        cnt = lo - a;
    }
    cnt = __shfl_sync(0xffffffffu, cnt, 0);
    float inv = 1.0f / fmaxf((float)cnt, 1.0f);
    float4 v = *(const float4*)&g_gsum[w * EMB + lane * 4];
    v.x *= inv; v.y *= inv; v.z *= inv; v.w *= inv;
    *(float4*)&g_ge[w * EMB + lane * 4] = v;
}

// ---------------- fused bucketing ----------------
__global__ void __launch_bounds__(1024) k_bucket(const int* __restrict__ ecl) {
    __shared__ int s_cnt[NC];
    __shared__ int s_start[NC];
    __shared__ int s_cur[NC];
    int t = threadIdx.x;
    if (t < NC) s_cnt[t] = 0;
    __syncthreads();
    for (int p = t; p < NP; p += 1024) atomicAdd(&s_cnt[ecl[p]], 1);
    __syncthreads();
    if (t == 0) {
        int a = 0;
        for (int c = 0; c < NC; c++) {
            s_start[c] = a;
            a += ((s_cnt[c] + 31) / 32) * 32;
        }
    }
    __syncthreads();
    for (int i = t; i < BUCKET_SLOTS; i += 1024) g_bucket[i] = -1;
    if (t < NC) s_cur[t] = s_start[t];
    __syncthreads();
    for (int p = t; p < NP; p += 1024) {
        int c = ecl[p];
        int pos = atomicAdd(&s_cur[c], 1);
        g_bucket[pos] = p;
    }
}

// ---------------- tf32 tensor-core regressor: 32 pairs per block ----------------
__global__ void __launch_bounds__(256) k_reg(
    const int* __restrict__ ddb, const int* __restrict__ ecl,
    const float* __restrict__ w1, const float* __restrict__ b1,
    const float* __restrict__ w2, const float* __restrict__ b2,
    float* __restrict__ out)
{
    __shared__ int      s_pid[32];
    __shared__ uint32_t s_pairU[32 * 268];
    __shared__ float    s_b1[HID];
    __shared__ float    s_w2[HID];
    __shared__ float    s_out[32];

    int tid = threadIdx.x;
    int warp = tid >> 5, lane = tid & 31;
    int base = blockIdx.x * 32;
    if (tid < 32) { s_pid[tid] = g_bucket[base + tid]; s_out[tid] = 0.f; }
    __syncthreads();

    int c = -1;
    for (int s = 0; s < 32 && c < 0; s++) {
        int p = s_pid[s];
        if (p >= 0) c = ecl[p];
    }
    if (c < 0) return;

    s_b1[tid] = b1[c * HID + tid];
    s_w2[tid] = w2[c * HID + tid];

    for (int i = tid; i < 32 * HID; i += 256) {
        int s = i >> 8, j = i & 255;
        int p = s_pid[s];
        float v = 0.0f;
        if (p >= 0) {
            int q = (j < 128) ? ddb[p] : ddb[NP + p];
            v = g_ge[q * EMB + (j & 127)];
        }
        s_pairU[s * 268 + j] = cvt_tf32(v);
    }
    __syncthreads();

    const float* Wc = w1 + c * (HID * HID);
    int n0 = warp * 32;
    int ra = lane >> 2, ca = lane & 3;

    float d[2][4][4];
#pragma unroll
    for (int mt = 0; mt < 2; mt++)
#pragma unroll
        for (int nt = 0; nt < 4; nt++)
            d[mt][nt][0] = d[mt][nt][1] = d[mt][nt][2] = d[mt][nt][3] = 0.f;

    for (int k0 = 0; k0 < HID; k0 += 8) {
        const uint32_t* pr = &s_pairU[ra * 268 + k0 + ca];
        uint32_t A[2][4];
        A[0][0] = pr[0];
        A[0][1] = pr[8 * 268];
        A[0][2] = pr[4];
        A[0][3] = pr[8 * 268 + 4];
        A[1][0] = pr[16 * 268];
        A[1][1] = pr[24 * 268];
        A[1][2] = pr[16 * 268 + 4];
        A[1][3] = pr[24 * 268 + 4];
        const float* wp0 = Wc + (k0 + ca) * HID + n0 + ra;
        const float* wp1 = wp0 + 4 * HID;
#pragma unroll
        for (int nt = 0; nt < 4; nt++) {
            uint32_t b0 = cvt_tf32(__ldg(wp0 + nt * 8));
            uint32_t b1v = cvt_tf32(__ldg(wp1 + nt * 8));
            mma_tf32(d[0][nt], A[0], b0, b1v);
            mma_tf32(d[1][nt], A[1], b0, b1v);
        }
    }

    float rowsum[2][2] = {{0.f, 0.f}, {0.f, 0.f}};
#pragma unroll
    for (int mt = 0; mt < 2; mt++) {
#pragma unroll
        for (int nt = 0; nt < 4; nt++) {
            int colb = n0 + nt * 8 + 2 * ca;
            float b1a = s_b1[colb],     w2a = s_w2[colb];
            float b1b = s_b1[colb + 1], w2b = s_w2[colb + 1];
            rowsum[mt][0] += fmaxf(d[mt][nt][0] + b1a, 0.f) * w2a
                           + fmaxf(d[mt][nt][1] + b1b, 0.f) * w2b;
            rowsum[mt][1] += fmaxf(d[mt][nt][2] + b1a, 0.f) * w2a
                           + fmaxf(d[mt][nt][3] + b1b, 0.f) * w2b;
        }
    }
#pragma unroll
    for (int mt = 0; mt < 2; mt++)
#pragma unroll
        for (int hi = 0; hi < 2; hi++) {
            float v = rowsum[mt][hi];
            v += __shfl_xor_sync(0xffffffffu, v, 1);
            v += __shfl_xor_sync(0xffffffffu, v, 2);
            if (ca == 0) atomicAdd(&s_out[mt * 16 + hi * 8 + ra], v);
        }
    __syncthreads();

    if (tid < 32) {
        int p = s_pid[tid];
        if (p >= 0) out[p] = s_out[tid] + b2[c];
    }
}

// ---------------- host launch ----------------
extern "C" void kernel_launch(void* const* d_in, const int* in_sizes, int n_in,
                              void* d_out, int out_size)
{
    const float* x    = (const float*)d_in[0];
    const float* c1w  = (const float*)d_in[1];
    const float* c1b  = (const float*)d_in[2];
    const float* c2w  = (const float*)d_in[3];
    const float* c2b  = (const float*)d_in[4];
    const float* rw1  = (const float*)d_in[5];
    const float* rb1  = (const float*)d_in[6];
    const float* rw2  = (const float*)d_in[7];
    const float* rb2  = (const float*)d_in[8];
    const int*   ei   = (const int*)d_in[9];
    const int*   bat  = (const int*)d_in[10];
    const int*   ddb  = (const int*)d_in[11];
    const int*   ecl  = (const int*)d_in[12];
    float* out = (float*)d_out;

    // side stream + events (created once; host resources, no device allocation)
    static cudaStream_t s1 = nullptr;
    static cudaEvent_t evFork = nullptr, evJoin = nullptr;
    if (s1 == nullptr) {
        cudaStreamCreateWithFlags(&s1, cudaStreamNonBlocking);
        cudaEventCreateWithFlags(&evFork, cudaEventDisableTiming);
        cudaEventCreateWithFlags(&evJoin, cudaEventDisableTiming);
    }

    void* icnt_ptr = nullptr;
    void* gsum_ptr = nullptr;
    cudaGetSymbolAddress(&icnt_ptr, g_icnt);
    cudaGetSymbolAddress(&gsum_ptr, g_gsum);

    const int T = 256;

    // fork: side branch runs work independent of the CSR chain
    cudaEventRecord(evFork, 0);
    cudaStreamWaitEvent(s1, evFork, 0);
    cudaMemsetAsync(gsum_ptr, 0, NG * EMB * sizeof(float), s1);
    k_tohalf<<<(NN * INCH / 4 + T - 1) / T, T, 0, s1>>>(x);
    k_bucket<<<1, 1024, 0, s1>>>(ecl);
    cudaEventRecord(evJoin, s1);

    // main branch: CSR build chain
    cudaMemsetAsync(icnt_ptr, 0, NN * sizeof(int), 0);
    k_icnt<<<(NE / 4 + T - 1) / T, T>>>(ei);
    k_scan1<<<NBLK, NPB>>>();
    k_scan2<<<1, 512>>>();
    k_scan3<<<NBLK, NPB>>>();
    k_fill<<<(NE / 4 + T - 1) / T, T>>>(ei);

    // join before the consumers of the side branch
    cudaStreamWaitEvent(0, evJoin, 0);

    // layer 1 + layer 2 + mean + regressor
    k_gcn1<<<(NN + 63) / 64, T>>>(c1w, c1b);
    k_gcn2<<<(NN + 63) / 64, T>>>(c2w, c2b, bat);
    k_ge<<<(NG * 32 + T - 1) / T, T>>>(bat);
    k_reg<<<REG_BLOCKS, T>>>(ddb, ecl, rw1, rb1, rw2, rb2, out);
}

// round 13
// speedup vs baseline: 1.5229x; 1.0325x over previous
#include <cuda_runtime.h>
#include <cuda_fp16.h>
#include <math.h>
#include <stdint.h>

#define NN 50000
#define NE 800000
#define NG 1024
#define NP 16384
#define NC 16
#define INCH 64
#define EMB 128
#define HID 256
#define BUCKET_SLOTS ((NP / 32 + NC) * 32)   // 16896
#define REG_BLOCKS (NP / 32 + NC)            // 528
#define NPB 128
#define NBLK ((NN + NPB - 1) / NPB)           // 391

// ---------------- scratch ----------------
__device__ float  g_dinv[NN];
__device__ int    g_icnt[NN];
__device__ int    g_rowptr[NN + 1];
__device__ int    g_rank[NE];
__device__ int    g_bsum[512];
__device__ int    g_csr[NE];
__device__ __half g_xh[NN * INCH];       // fp16 copy of x
__device__ __half g_hws[NN * EMB];       // fp16 dinv*relu(h1)
__device__ float  g_gsum[NG * EMB];
__device__ float  g_ginv[NG];
__device__ int    g_bucket[BUCKET_SLOTS];

// ---------------- helpers ----------------
__device__ __forceinline__ void red_add_v2(float* addr, float a, float b) {
    asm volatile("red.global.add.v2.f32 [%0], {%1, %2};"
                 :: "l"(addr), "f"(a), "f"(b) : "memory");
}
__device__ __forceinline__ float4 f4add(float4 a, float4 b) {
    return make_float4(a.x + b.x, a.y + b.y, a.z + b.z, a.w + b.w);
}
__device__ __forceinline__ uint32_t cvt_tf32(float f) {
    uint32_t u;
    asm("cvt.rna.tf32.f32 %0, %1;" : "=r"(u) : "f"(f));
    return u;
}
__device__ __forceinline__ void mma_tf32(float* d, const uint32_t* a,
                                         uint32_t b0, uint32_t b1) {
    asm("mma.sync.aligned.m16n8k8.row.col.f32.tf32.tf32.f32 "
        "{%0,%1,%2,%3}, {%4,%5,%6,%7}, {%8,%9}, {%0,%1,%2,%3};"
        : "+f"(d[0]), "+f"(d[1]), "+f"(d[2]), "+f"(d[3])
        : "r"(a[0]), "r"(a[1]), "r"(a[2]), "r"(a[3]), "r"(b0), "r"(b1));
}
// load 4 consecutive halves as float4 (8-byte load)
__device__ __forceinline__ float4 ldh4(const __half* p) {
    uint2 u = *(const uint2*)p;
    __half2 h0 = *(__half2*)&u.x, h1 = *(__half2*)&u.y;
    float2 f0 = __half22float2(h0), f1 = __half22float2(h1);
    return make_float4(f0.x, f0.y, f1.x, f1.y);
}

// ---------------- x -> fp16 ----------------
__global__ void k_tohalf(const float* __restrict__ x) {
    int i = blockIdx.x * blockDim.x + threadIdx.x;
    if (i < NN * INCH / 4) {
        float4 v = ((const float4*)x)[i];
        __half2 h0 = __floats2half2_rn(v.x, v.y);
        __half2 h1 = __floats2half2_rn(v.z, v.w);
        uint2 u = make_uint2(*(uint32_t*)&h0, *(uint32_t*)&h1);
        ((uint2*)g_xh)[i] = u;
    }
}

// ---------------- per-graph 1/cnt (side stream; batch is sorted) ----------------
__global__ void k_cntg(const int* __restrict__ batch) {
    int g = blockIdx.x * blockDim.x + threadIdx.x;
    if (g >= NG) return;
    int lo = 0, hi = NN;
    while (lo < hi) { int m = (lo + hi) >> 1; if (batch[m] < g) lo = m + 1; else hi = m; }
    int a = lo;
    hi = NN;
    while (lo < hi) { int m = (lo + hi) >> 1; if (batch[m] < g + 1) lo = m + 1; else hi = m; }
    g_ginv[g] = 1.0f / fmaxf((float)(lo - a), 1.0f);
}

// ---------------- degree histogram + per-edge rank (4 edges per thread) ----------------
__global__ void k_icnt(const int* __restrict__ ei) {
    int i = blockIdx.x * blockDim.x + threadIdx.x;
    if (i < NE / 4) {
        int4 t = ((const int4*)(ei + NE))[i];
        int4 k;
        k.x = atomicAdd(&g_icnt[t.x], 1);
        k.y = atomicAdd(&g_icnt[t.y], 1);
        k.z = atomicAdd(&g_icnt[t.z], 1);
        k.w = atomicAdd(&g_icnt[t.w], 1);
        ((int4*)g_rank)[i] = k;
    }
}

// ---------------- prefix scan (+ fused dinv) ----------------
__global__ void k_scan1() {
    __shared__ int sm[NPB];
    int i = blockIdx.x * NPB + threadIdx.x;
    int v = (i < NN) ? g_icnt[i] : 0;
    if (i < NN) g_dinv[i] = rsqrtf((float)(v + 1));
    sm[threadIdx.x] = v;
    __syncthreads();
    for (int s = NPB / 2; s > 0; s >>= 1) {
        if (threadIdx.x < s) sm[threadIdx.x] += sm[threadIdx.x + s];
        __syncthreads();
    }
    if (threadIdx.x == 0) g_bsum[blockIdx.x] = sm[0];
}
__global__ void k_scan2() {
    __shared__ int sm[512];
    int t = threadIdx.x;
    int v = (t < NBLK) ? g_bsum[t] : 0;
    sm[t] = v;
    __syncthreads();
    for (int s = 1; s < 512; s <<= 1) {
        int a = (t >= s) ? sm[t - s] : 0;
        __syncthreads();
        sm[t] += a;
        __syncthreads();
    }
    if (t < NBLK) g_bsum[t] = sm[t] - v;
}
__global__ void k_scan3() {
    __shared__ int sm[NPB];
    int t = threadIdx.x;
    int i = blockIdx.x * NPB + t;
    int v = (i < NN) ? g_icnt[i] : 0;
    sm[t] = v;
    __syncthreads();
    for (int s = 1; s < NPB; s <<= 1) {
        int a = (t >= s) ? sm[t - s] : 0;
        __syncthreads();
        sm[t] += a;
        __syncthreads();
    }
    if (i < NN) {
        g_rowptr[i] = g_bsum[blockIdx.x] + sm[t] - v;
        if (i == NN - 1) g_rowptr[NN] = NE;
    }
}

// ---------------- fill without atomics: csr[rowptr[c]+rank] = src ----------------
__global__ void k_fill(const int* __restrict__ ei) {
    int i = blockIdx.x * blockDim.x + threadIdx.x;
    if (i < NE / 4) {
        int4 c = ((const int4*)(ei + NE))[i];
        int4 r = ((const int4*)ei)[i];
        int4 k = ((const int4*)g_rank)[i];
        g_csr[g_rowptr[c.x] + k.x] = r.x;
        g_csr[g_rowptr[c.y] + k.y] = r.y;
        g_csr[g_rowptr[c.z] + k.z] = r.z;
        g_csr[g_rowptr[c.w] + k.w] = r.w;
    }
}

// ---------------- fused gather(fp16) + tf32 GEMM, layer 1 (K=64) ----------------
__global__ void __launch_bounds__(256) k_gcn1(
    const float* __restrict__ W, const float* __restrict__ bias)
{
    constexpr int K = 64, KP = 68, BM = 64;
    __shared__ uint32_t sXu[BM * KP];

    int tid = threadIdx.x;
    int warp = tid >> 5, lane = tid & 31;
    int row0 = blockIdx.x * BM;

    // gather phase: half-warp per node (16 lanes x 4 halves = 64 cols)
    int half = lane >> 4, l = lane & 15;
    for (int it = 0; it < 4; it++) {
        int nl = warp * 8 + it * 2 + half;
        int node = row0 + nl;
        float4 acc = make_float4(0.f, 0.f, 0.f, 0.f);
        if (node < NN) {
            float dn = g_dinv[node];
            acc = ldh4(&g_xh[node * INCH + l * 4]);
            acc.x *= dn; acc.y *= dn; acc.z *= dn; acc.w *= dn;
            int e = g_rowptr[node], end = g_rowptr[node + 1];
            for (; e + 4 <= end; e += 4) {
                int s0 = g_csr[e], s1 = g_csr[e + 1], s2 = g_csr[e + 2], s3 = g_csr[e + 3];
                float4 a0 = ldh4(&g_xh[s0 * INCH + l * 4]);
                float4 a1 = ldh4(&g_xh[s1 * INCH + l * 4]);
                float4 a2 = ldh4(&g_xh[s2 * INCH + l * 4]);
                float4 a3 = ldh4(&g_xh[s3 * INCH + l * 4]);
                float d0 = g_dinv[s0], d1 = g_dinv[s1], d2 = g_dinv[s2], d3 = g_dinv[s3];
                acc.x = fmaf(d0, a0.x, fmaf(d1, a1.x, fmaf(d2, a2.x, fmaf(d3, a3.x, acc.x))));
                acc.y = fmaf(d0, a0.y, fmaf(d1, a1.y, fmaf(d2, a2.y, fmaf(d3, a3.y, acc.y))));
                acc.z = fmaf(d0, a0.z, fmaf(d1, a1.z, fmaf(d2, a2.z, fmaf(d3, a3.z, acc.z))));
                acc.w = fmaf(d0, a0.w, fmaf(d1, a1.w, fmaf(d2, a2.w, fmaf(d3, a3.w, acc.w))));
            }
            for (; e < end; e++) {
                int s = g_csr[e];
                float4 a = ldh4(&g_xh[s * INCH + l * 4]);
                float ds = g_dinv[s];
                acc.x = fmaf(ds, a.x, acc.x);
                acc.y = fmaf(ds, a.y, acc.y);
                acc.z = fmaf(ds, a.z, acc.z);
                acc.w = fmaf(ds, a.w, acc.w);
            }
            acc.x *= dn; acc.y *= dn; acc.z *= dn; acc.w *= dn;  // left norm
        }
        uint4 uv = make_uint4(cvt_tf32(acc.x), cvt_tf32(acc.y),
                              cvt_tf32(acc.z), cvt_tf32(acc.w));
        *(uint4*)&sXu[nl * KP + l * 4] = uv;
    }
    __syncthreads();

    // tf32 GEMM
    int mt = warp & 3, nh = warp >> 2;
    int ra = lane >> 2, ca = lane & 3;
    float d[8][4];
#pragma unroll
    for (int nt = 0; nt < 8; nt++)
        d[nt][0] = d[nt][1] = d[nt][2] = d[nt][3] = 0.f;

#pragma unroll
    for (int k0 = 0; k0 < K; k0 += 8) {
        const uint32_t* pa = &sXu[(mt * 16 + ra) * KP + k0 + ca];
        uint32_t A[4] = { pa[0], pa[8 * KP], pa[4], pa[8 * KP + 4] };
        const float* wb = &W[(k0 + ca) * 128 + nh * 64 + ra];
#pragma unroll
        for (int nt = 0; nt < 8; nt++) {
            uint32_t b0 = cvt_tf32(__ldg(wb + nt * 8));
            uint32_t b1 = cvt_tf32(__ldg(wb + 4 * 128 + nt * 8));
            mma_tf32(d[nt], A, b0, b1);
        }
    }

    // epilogue: bias + relu + dinv -> g_hws (fp16)
    int gr0 = row0 + mt * 16 + ra;
    int gr1 = gr0 + 8;
    float dv0 = (gr0 < NN) ? g_dinv[gr0] : 0.f;
    float dv1 = (gr1 < NN) ? g_dinv[gr1] : 0.f;
#pragma unroll
    for (int nt = 0; nt < 8; nt++) {
        int col = nh * 64 + nt * 8 + 2 * ca;
        float bx = __ldg(&bias[col]), by = __ldg(&bias[col + 1]);
        if (gr0 < NN) {
            __half2 o = __floats2half2_rn(fmaxf(d[nt][0] + bx, 0.f) * dv0,
                                          fmaxf(d[nt][1] + by, 0.f) * dv0);
            *(__half2*)&g_hws[gr0 * EMB + col] = o;
        }
        if (gr1 < NN) {
            __half2 o = __floats2half2_rn(fmaxf(d[nt][2] + bx, 0.f) * dv1,
                                          fmaxf(d[nt][3] + by, 0.f) * dv1);
            *(__half2*)&g_hws[gr1 * EMB + col] = o;
        }
    }
}

// ---------------- fused gather(fp16) + tf32 GEMM + pool, layer 2 (K=128) ----------------
__global__ void __launch_bounds__(256) k_gcn2(
    const float* __restrict__ W, const float* __restrict__ bias,
    const int* __restrict__ batch)
{
    constexpr int K = 128, KP = 132, BM = 64;
    __shared__ uint32_t sXu[BM * KP];

    int tid = threadIdx.x;
    int warp = tid >> 5, lane = tid & 31;
    int row0 = blockIdx.x * BM;

    // gather phase: warp per node, lane handles 4 halves (8B loads)
    for (int it = 0; it < 8; it++) {
        int nl = warp * 8 + it;
        int node = row0 + nl;
        float4 acc = make_float4(0.f, 0.f, 0.f, 0.f);
        if (node < NN) {
            acc = ldh4(&g_hws[node * EMB + lane * 4]);  // self
            int e = g_rowptr[node], end = g_rowptr[node + 1];
            for (; e + 4 <= end; e += 4) {
                int s0 = g_csr[e], s1 = g_csr[e + 1], s2 = g_csr[e + 2], s3 = g_csr[e + 3];
                float4 a0 = ldh4(&g_hws[s0 * EMB + lane * 4]);
                float4 a1 = ldh4(&g_hws[s1 * EMB + lane * 4]);
                float4 a2 = ldh4(&g_hws[s2 * EMB + lane * 4]);
                float4 a3 = ldh4(&g_hws[s3 * EMB + lane * 4]);
                acc = f4add(acc, f4add(f4add(a0, a1), f4add(a2, a3)));
            }
            for (; e < end; e++) {
                int s = g_csr[e];
                acc = f4add(acc, ldh4(&g_hws[s * EMB + lane * 4]));
            }
            float dn = g_dinv[node];
            acc.x *= dn; acc.y *= dn; acc.z *= dn; acc.w *= dn;
        }
        uint4 uv = make_uint4(cvt_tf32(acc.x), cvt_tf32(acc.y),
                              cvt_tf32(acc.z), cvt_tf32(acc.w));
        *(uint4*)&sXu[nl * KP + lane * 4] = uv;
    }
    __syncthreads();

    // tf32 GEMM
    int mt = warp & 3, nh = warp >> 2;
    int ra = lane >> 2, ca = lane & 3;
    float d[8][4];
#pragma unroll
    for (int nt = 0; nt < 8; nt++)
        d[nt][0] = d[nt][1] = d[nt][2] = d[nt][3] = 0.f;

#pragma unroll 4
    for (int k0 = 0; k0 < K; k0 += 8) {
        const uint32_t* pa = &sXu[(mt * 16 + ra) * KP + k0 + ca];
        uint32_t A[4] = { pa[0], pa[8 * KP], pa[4], pa[8 * KP + 4] };
        const float* wb = &W[(k0 + ca) * 128 + nh * 64 + ra];
#pragma unroll
        for (int nt = 0; nt < 8; nt++) {
            uint32_t b0 = cvt_tf32(__ldg(wb + nt * 8));
            uint32_t b1 = cvt_tf32(__ldg(wb + 4 * 128 + nt * 8));
            mma_tf32(d[nt], A, b0, b1);
        }
    }

    // epilogue: bias + relu + pooled red.add into g_gsum
    int gr0 = row0 + mt * 16 + ra;
    int gr1 = gr0 + 8;
    int b0i = (gr0 < NN) ? batch[gr0] : 0;
    int b1i = (gr1 < NN) ? batch[gr1] : 0;
#pragma unroll
    for (int nt = 0; nt < 8; nt++) {
        int col = nh * 64 + nt * 8 + 2 * ca;
        float bx = __ldg(&bias[col]), by = __ldg(&bias[col + 1]);
        if (gr0 < NN)
            red_add_v2(&g_gsum[b0i * EMB + col],
                       fmaxf(d[nt][0] + bx, 0.f), fmaxf(d[nt][1] + by, 0.f));
        if (gr1 < NN)
            red_add_v2(&g_gsum[b1i * EMB + col],
                       fmaxf(d[nt][2] + bx, 0.f), fmaxf(d[nt][3] + by, 0.f));
    }
}

// ---------------- fused bucketing ----------------
__global__ void __launch_bounds__(1024) k_bucket(const int* __restrict__ ecl) {
    __shared__ int s_cnt[NC];
    __shared__ int s_start[NC];
    __shared__ int s_cur[NC];
    int t = threadIdx.x;
    if (t < NC) s_cnt[t] = 0;
    __syncthreads();
    for (int p = t; p < NP; p += 1024) atomicAdd(&s_cnt[ecl[p]], 1);
    __syncthreads();
    if (t == 0) {
        int a = 0;
        for (int c = 0; c < NC; c++) {
            s_start[c] = a;
            a += ((s_cnt[c] + 31) / 32) * 32;
        }
    }
    __syncthreads();
    for (int i = t; i < BUCKET_SLOTS; i += 1024) g_bucket[i] = -1;
    if (t < NC) s_cur[t] = s_start[t];
    __syncthreads();
    for (int p = t; p < NP; p += 1024) {
        int c = ecl[p];
        int pos = atomicAdd(&s_cur[c], 1);
        g_bucket[pos] = p;
    }
}

// ---------------- tf32 tensor-core regressor: 32 pairs per block ----------------
// (mean normalization folded in: pair value = gsum[q]*ginv[q])
__global__ void __launch_bounds__(256) k_reg(
    const int* __restrict__ ddb, const int* __restrict__ ecl,
    const float* __restrict__ w1, const float* __restrict__ b1,
    const float* __restrict__ w2, const float* __restrict__ b2,
    float* __restrict__ out)
{
    __shared__ int      s_pid[32];
    __shared__ uint32_t s_pairU[32 * 268];
    __shared__ float    s_b1[HID];
    __shared__ float    s_w2[HID];
    __shared__ float    s_out[32];

    int tid = threadIdx.x;
    int warp = tid >> 5, lane = tid & 31;
    int base = blockIdx.x * 32;
    if (tid < 32) { s_pid[tid] = g_bucket[base + tid]; s_out[tid] = 0.f; }
    __syncthreads();

    int c = -1;
    for (int s = 0; s < 32 && c < 0; s++) {
        int p = s_pid[s];
        if (p >= 0) c = ecl[p];
    }
    if (c < 0) return;

    s_b1[tid] = b1[c * HID + tid];
    s_w2[tid] = w2[c * HID + tid];

    for (int i = tid; i < 32 * HID; i += 256) {
        int s = i >> 8, j = i & 255;
        int p = s_pid[s];
        float v = 0.0f;
        if (p >= 0) {
            int q = (j < 128) ? ddb[p] : ddb[NP + p];
            v = g_gsum[q * EMB + (j & 127)] * g_ginv[q];
        }
        s_pairU[s * 268 + j] = cvt_tf32(v);
    }
    __syncthreads();

    const float* Wc = w1 + c * (HID * HID);
    int n0 = warp * 32;
    int ra = lane >> 2, ca = lane & 3;

    float d[2][4][4];
#pragma unroll
    for (int mt = 0; mt < 2; mt++)
#pragma unroll
        for (int nt = 0; nt < 4; nt++)
            d[mt][nt][0] = d[mt][nt][1] = d[mt][nt][2] = d[mt][nt][3] = 0.f;

    for (int k0 = 0; k0 < HID; k0 += 8) {
        const uint32_t* pr = &s_pairU[ra * 268 + k0 + ca];
        uint32_t A[2][4];
        A[0][0] = pr[0];
        A[0][1] = pr[8 * 268];
        A[0][2] = pr[4];
        A[0][3] = pr[8 * 268 + 4];
        A[1][0] = pr[16 * 268];
        A[1][1] = pr[24 * 268];
        A[1][2] = pr[16 * 268 + 4];
        A[1][3] = pr[24 * 268 + 4];
        const float* wp0 = Wc + (k0 + ca) * HID + n0 + ra;
        const float* wp1 = wp0 + 4 * HID;
#pragma unroll
        for (int nt = 0; nt < 4; nt++) {
            uint32_t b0 = cvt_tf32(__ldg(wp0 + nt * 8));
            uint32_t b1v = cvt_tf32(__ldg(wp1 + nt * 8));
            mma_tf32(d[0][nt], A[0], b0, b1v);
            mma_tf32(d[1][nt], A[1], b0, b1v);
        }
    }

    float rowsum[2][2] = {{0.f, 0.f}, {0.f, 0.f}};
#pragma unroll
    for (int mt = 0; mt < 2; mt++) {
#pragma unroll
        for (int nt = 0; nt < 4; nt++) {
            int colb = n0 + nt * 8 + 2 * ca;
            float b1a = s_b1[colb],     w2a = s_w2[colb];
            float b1b = s_b1[colb + 1], w2b = s_w2[colb + 1];
            rowsum[mt][0] += fmaxf(d[mt][nt][0] + b1a, 0.f) * w2a
                           + fmaxf(d[mt][nt][1] + b1b, 0.f) * w2b;
            rowsum[mt][1] += fmaxf(d[mt][nt][2] + b1a, 0.f) * w2a
                           + fmaxf(d[mt][nt][3] + b1b, 0.f) * w2b;
        }
    }
#pragma unroll
    for (int mt = 0; mt < 2; mt++)
#pragma unroll
        for (int hi = 0; hi < 2; hi++) {
            float v = rowsum[mt][hi];
            v += __shfl_xor_sync(0xffffffffu, v, 1);
            v += __shfl_xor_sync(0xffffffffu, v, 2);
            if (ca == 0) atomicAdd(&s_out[mt * 16 + hi * 8 + ra], v);
        }
    __syncthreads();

    if (tid < 32) {
        int p = s_pid[tid];
        if (p >= 0) out[p] = s_out[tid] + b2[c];
    }
}

// ---------------- host launch ----------------
extern "C" void kernel_launch(void* const* d_in, const int* in_sizes, int n_in,
                              void* d_out, int out_size)
{
    const float* x    = (const float*)d_in[0];
    const float* c1w  = (const float*)d_in[1];
    const float* c1b  = (const float*)d_in[2];
    const float* c2w  = (const float*)d_in[3];
    const float* c2b  = (const float*)d_in[4];
    const float* rw1  = (const float*)d_in[5];
    const float* rb1  = (const float*)d_in[6];
    const float* rw2  = (const float*)d_in[7];
    const float* rb2  = (const float*)d_in[8];
    const int*   ei   = (const int*)d_in[9];
    const int*   bat  = (const int*)d_in[10];
    const int*   ddb  = (const int*)d_in[11];
    const int*   ecl  = (const int*)d_in[12];
    float* out = (float*)d_out;

    // side stream + events (created once; host resources, no device allocation)
    static cudaStream_t s1 = nullptr;
    static cudaEvent_t evFork = nullptr, evJoin = nullptr;
    if (s1 == nullptr) {
        cudaStreamCreateWithFlags(&s1, cudaStreamNonBlocking);
        cudaEventCreateWithFlags(&evFork, cudaEventDisableTiming);
        cudaEventCreateWithFlags(&evJoin, cudaEventDisableTiming);
    }

    void* icnt_ptr = nullptr;
    void* gsum_ptr = nullptr;
    cudaGetSymbolAddress(&icnt_ptr, g_icnt);
    cudaGetSymbolAddress(&gsum_ptr, g_gsum);

    const int T = 256;

    // fork: side branch runs work independent of the CSR chain
    cudaEventRecord(evFork, 0);
    cudaStreamWaitEvent(s1, evFork, 0);
    cudaMemsetAsync(gsum_ptr, 0, NG * EMB * sizeof(float), s1);
    k_tohalf<<<(NN * INCH / 4 + T - 1) / T, T, 0, s1>>>(x);
    k_cntg<<<(NG + T - 1) / T, T, 0, s1>>>(bat);
    k_bucket<<<1, 1024, 0, s1>>>(ecl);
    cudaEventRecord(evJoin, s1);

    // main branch: CSR build chain
    cudaMemsetAsync(icnt_ptr, 0, NN * sizeof(int), 0);
    k_icnt<<<(NE / 4 + T - 1) / T, T>>>(ei);
    k_scan1<<<NBLK, NPB>>>();
    k_scan2<<<1, 512>>>();
    k_scan3<<<NBLK, NPB>>>();
    k_fill<<<(NE / 4 + T - 1) / T, T>>>(ei);

    // join before the consumers of the side branch
    cudaStreamWaitEvent(0, evJoin, 0);

    // layer 1 + layer 2 + regressor (mean folded into k_reg)
    k_gcn1<<<(NN + 63) / 64, T>>>(c1w, c1b);
    k_gcn2<<<(NN + 63) / 64, T>>>(c2w, c2b, bat);
    k_reg<<<REG_BLOCKS, T>>>(ddb, ecl, rw1, rb1, rw2, rb2, out);
}

// round 14
// speedup vs baseline: 1.5555x; 1.0214x over previous
#include <cuda_runtime.h>
#include <cuda_fp16.h>
#include <math.h>
#include <stdint.h>

#define NN 50000
#define NE 800000
#define NG 1024
#define NP 16384
#define NC 16
#define INCH 64
#define EMB 128
#define HID 256
#define BUCKET_SLOTS ((NP / 32 + NC) * 32)   // 16896
#define REG_BLOCKS (NP / 32 + NC)            // 528
#define NPB 128
#define NBLK ((NN + NPB - 1) / NPB)           // 391

// ---------------- scratch ----------------
__device__ float  g_dinv[NN];
__device__ int    g_icnt[NN];
__device__ int    g_rowptr[NN + 1];
__device__ int    g_rank[NE];
__device__ int    g_bsum[512];
__device__ int    g_csr[NE];
__device__ __half g_xh[NN * INCH];       // fp16 copy of x
__device__ __half g_hws[NN * EMB];       // fp16 dinv*relu(h1)
__device__ float  g_gsum[NG * EMB];
__device__ float  g_ginv[NG];
__device__ int    g_bucket[BUCKET_SLOTS];

// ---------------- helpers ----------------
__device__ __forceinline__ void red_add_v2(float* addr, float a, float b) {
    asm volatile("red.global.add.v2.f32 [%0], {%1, %2};"
                 :: "l"(addr), "f"(a), "f"(b) : "memory");
}
__device__ __forceinline__ float4 f4add(float4 a, float4 b) {
    return make_float4(a.x + b.x, a.y + b.y, a.z + b.z, a.w + b.w);
}
__device__ __forceinline__ uint32_t cvt_tf32(float f) {
    uint32_t u;
    asm("cvt.rna.tf32.f32 %0, %1;" : "=r"(u) : "f"(f));
    return u;
}
__device__ __forceinline__ void mma_tf32(float* d, const uint32_t* a,
                                         uint32_t b0, uint32_t b1) {
    asm("mma.sync.aligned.m16n8k8.row.col.f32.tf32.tf32.f32 "
        "{%0,%1,%2,%3}, {%4,%5,%6,%7}, {%8,%9}, {%0,%1,%2,%3};"
        : "+f"(d[0]), "+f"(d[1]), "+f"(d[2]), "+f"(d[3])
        : "r"(a[0]), "r"(a[1]), "r"(a[2]), "r"(a[3]), "r"(b0), "r"(b1));
}
// load 4 consecutive halves as float4 (8-byte load)
__device__ __forceinline__ float4 ldh4(const __half* p) {
    uint2 u = *(const uint2*)p;
    __half2 h0 = *(__half2*)&u.x, h1 = *(__half2*)&u.y;
    float2 f0 = __half22float2(h0), f1 = __half22float2(h1);
    return make_float4(f0.x, f0.y, f1.x, f1.y);
}

// ---------------- x -> fp16 ----------------
__global__ void k_tohalf(const float* __restrict__ x) {
    int i = blockIdx.x * blockDim.x + threadIdx.x;
    if (i < NN * INCH / 4) {
        float4 v = ((const float4*)x)[i];
        __half2 h0 = __floats2half2_rn(v.x, v.y);
        __half2 h1 = __floats2half2_rn(v.z, v.w);
        uint2 u = make_uint2(*(uint32_t*)&h0, *(uint32_t*)&h1);
        ((uint2*)g_xh)[i] = u;
    }
}

// ---------------- per-graph 1/cnt (side stream; batch is sorted) ----------------
__global__ void k_cntg(const int* __restrict__ batch) {
    int g = blockIdx.x * blockDim.x + threadIdx.x;
    if (g >= NG) return;
    int lo = 0, hi = NN;
    while (lo < hi) { int m = (lo + hi) >> 1; if (batch[m] < g) lo = m + 1; else hi = m; }
    int a = lo;
    hi = NN;
    while (lo < hi) { int m = (lo + hi) >> 1; if (batch[m] < g + 1) lo = m + 1; else hi = m; }
    g_ginv[g] = 1.0f / fmaxf((float)(lo - a), 1.0f);
}

// ---------------- degree histogram + per-edge rank (8 edges per thread) ----------------
__global__ void k_icnt(const int* __restrict__ ei) {
    int i = blockIdx.x * blockDim.x + threadIdx.x;
    int i0 = i * 2, i1 = i * 2 + 1;
    if (i0 < NE / 4) {
        int4 ta = ((const int4*)(ei + NE))[i0];
        bool has_b = (i1 < NE / 4);
        int4 tb = has_b ? ((const int4*)(ei + NE))[i1] : make_int4(0, 0, 0, 0);
        int4 ka, kb;
        ka.x = atomicAdd(&g_icnt[ta.x], 1);
        ka.y = atomicAdd(&g_icnt[ta.y], 1);
        ka.z = atomicAdd(&g_icnt[ta.z], 1);
        ka.w = atomicAdd(&g_icnt[ta.w], 1);
        if (has_b) {
            kb.x = atomicAdd(&g_icnt[tb.x], 1);
            kb.y = atomicAdd(&g_icnt[tb.y], 1);
            kb.z = atomicAdd(&g_icnt[tb.z], 1);
            kb.w = atomicAdd(&g_icnt[tb.w], 1);
        }
        ((int4*)g_rank)[i0] = ka;
        if (has_b) ((int4*)g_rank)[i1] = kb;
    }
}

// ---------------- prefix scan (+ fused dinv) ----------------
__global__ void k_scan1() {
    __shared__ int sm[NPB];
    int i = blockIdx.x * NPB + threadIdx.x;
    int v = (i < NN) ? g_icnt[i] : 0;
    if (i < NN) g_dinv[i] = rsqrtf((float)(v + 1));
    sm[threadIdx.x] = v;
    __syncthreads();
    for (int s = NPB / 2; s > 0; s >>= 1) {
        if (threadIdx.x < s) sm[threadIdx.x] += sm[threadIdx.x + s];
        __syncthreads();
    }
    if (threadIdx.x == 0) g_bsum[blockIdx.x] = sm[0];
}
__global__ void k_scan2() {
    __shared__ int sm[512];
    int t = threadIdx.x;
    int v = (t < NBLK) ? g_bsum[t] : 0;
    sm[t] = v;
    __syncthreads();
    for (int s = 1; s < 512; s <<= 1) {
        int a = (t >= s) ? sm[t - s] : 0;
        __syncthreads();
        sm[t] += a;
        __syncthreads();
    }
    if (t < NBLK) g_bsum[t] = sm[t] - v;
}
__global__ void k_scan3() {
    __shared__ int sm[NPB];
    int t = threadIdx.x;
    int i = blockIdx.x * NPB + t;
    int v = (i < NN) ? g_icnt[i] : 0;
    sm[t] = v;
    __syncthreads();
    for (int s = 1; s < NPB; s <<= 1) {
        int a = (t >= s) ? sm[t - s] : 0;
        __syncthreads();
        sm[t] += a;
        __syncthreads();
    }
    if (i < NN) {
        g_rowptr[i] = g_bsum[blockIdx.x] + sm[t] - v;
        if (i == NN - 1) g_rowptr[NN] = NE;
    }
}

// ---------------- fill without atomics: csr[rowptr[c]+rank] = src ----------------
__global__ void k_fill(const int* __restrict__ ei) {
    int i = blockIdx.x * blockDim.x + threadIdx.x;
    if (i < NE / 4) {
        int4 c = ((const int4*)(ei + NE))[i];
        int4 r = ((const int4*)ei)[i];
        int4 k = ((const int4*)g_rank)[i];
        g_csr[g_rowptr[c.x] + k.x] = r.x;
        g_csr[g_rowptr[c.y] + k.y] = r.y;
        g_csr[g_rowptr[c.z] + k.z] = r.z;
        g_csr[g_rowptr[c.w] + k.w] = r.w;
    }
}

// ---------------- fused gather(fp16) + tf32 GEMM, layer 1 (K=64) ----------------
__global__ void __launch_bounds__(256, 3) k_gcn1(
    const float* __restrict__ W, const float* __restrict__ bias)
{
    constexpr int K = 64, KP = 68, BM = 64;
    __shared__ uint32_t sXu[BM * KP];

    int tid = threadIdx.x;
    int warp = tid >> 5, lane = tid & 31;
    int row0 = blockIdx.x * BM;

    // gather phase: half-warp per node (16 lanes x 4 halves = 64 cols)
    int half = lane >> 4, l = lane & 15;
    for (int it = 0; it < 4; it++) {
        int nl = warp * 8 + it * 2 + half;
        int node = row0 + nl;
        float4 acc = make_float4(0.f, 0.f, 0.f, 0.f);
        if (node < NN) {
            float dn = g_dinv[node];
            acc = ldh4(&g_xh[node * INCH + l * 4]);
            acc.x *= dn; acc.y *= dn; acc.z *= dn; acc.w *= dn;
            int e = g_rowptr[node], end = g_rowptr[node + 1];
            for (; e + 4 <= end; e += 4) {
                int s0 = g_csr[e], s1 = g_csr[e + 1], s2 = g_csr[e + 2], s3 = g_csr[e + 3];
                float4 a0 = ldh4(&g_xh[s0 * INCH + l * 4]);
                float4 a1 = ldh4(&g_xh[s1 * INCH + l * 4]);
                float4 a2 = ldh4(&g_xh[s2 * INCH + l * 4]);
                float4 a3 = ldh4(&g_xh[s3 * INCH + l * 4]);
                float d0 = g_dinv[s0], d1 = g_dinv[s1], d2 = g_dinv[s2], d3 = g_dinv[s3];
                acc.x = fmaf(d0, a0.x, fmaf(d1, a1.x, fmaf(d2, a2.x, fmaf(d3, a3.x, acc.x))));
                acc.y = fmaf(d0, a0.y, fmaf(d1, a1.y, fmaf(d2, a2.y, fmaf(d3, a3.y, acc.y))));
                acc.z = fmaf(d0, a0.z, fmaf(d1, a1.z, fmaf(d2, a2.z, fmaf(d3, a3.z, acc.z))));
                acc.w = fmaf(d0, a0.w, fmaf(d1, a1.w, fmaf(d2, a2.w, fmaf(d3, a3.w, acc.w))));
            }
            for (; e < end; e++) {
                int s = g_csr[e];
                float4 a = ldh4(&g_xh[s * INCH + l * 4]);
                float ds = g_dinv[s];
                acc.x = fmaf(ds, a.x, acc.x);
                acc.y = fmaf(ds, a.y, acc.y);
                acc.z = fmaf(ds, a.z, acc.z);
                acc.w = fmaf(ds, a.w, acc.w);
            }
            acc.x *= dn; acc.y *= dn; acc.z *= dn; acc.w *= dn;  // left norm
        }
        uint4 uv = make_uint4(cvt_tf32(acc.x), cvt_tf32(acc.y),
                              cvt_tf32(acc.z), cvt_tf32(acc.w));
        *(uint4*)&sXu[nl * KP + l * 4] = uv;
    }
    __syncthreads();

    // tf32 GEMM
    int mt = warp & 3, nh = warp >> 2;
    int ra = lane >> 2, ca = lane & 3;
    float d[8][4];
#pragma unroll
    for (int nt = 0; nt < 8; nt++)
        d[nt][0] = d[nt][1] = d[nt][2] = d[nt][3] = 0.f;

#pragma unroll
    for (int k0 = 0; k0 < K; k0 += 8) {
        const uint32_t* pa = &sXu[(mt * 16 + ra) * KP + k0 + ca];
        uint32_t A[4] = { pa[0], pa[8 * KP], pa[4], pa[8 * KP + 4] };
        const float* wb = &W[(k0 + ca) * 128 + nh * 64 + ra];
#pragma unroll
        for (int nt = 0; nt < 8; nt++) {
            uint32_t b0 = cvt_tf32(__ldg(wb + nt * 8));
            uint32_t b1 = cvt_tf32(__ldg(wb + 4 * 128 + nt * 8));
            mma_tf32(d[nt], A, b0, b1);
        }
    }

    // epilogue: bias + relu + dinv -> g_hws (fp16)
    int gr0 = row0 + mt * 16 + ra;
    int gr1 = gr0 + 8;
    float dv0 = (gr0 < NN) ? g_dinv[gr0] : 0.f;
    float dv1 = (gr1 < NN) ? g_dinv[gr1] : 0.f;
#pragma unroll
    for (int nt = 0; nt < 8; nt++) {
        int col = nh * 64 + nt * 8 + 2 * ca;
        float bx = __ldg(&bias[col]), by = __ldg(&bias[col + 1]);
        if (gr0 < NN) {
            __half2 o = __floats2half2_rn(fmaxf(d[nt][0] + bx, 0.f) * dv0,
                                          fmaxf(d[nt][1] + by, 0.f) * dv0);
            *(__half2*)&g_hws[gr0 * EMB + col] = o;
        }
        if (gr1 < NN) {
            __half2 o = __floats2half2_rn(fmaxf(d[nt][2] + bx, 0.f) * dv1,
                                          fmaxf(d[nt][3] + by, 0.f) * dv1);
            *(__half2*)&g_hws[gr1 * EMB + col] = o;
        }
    }
}

// ---------------- fused gather(fp16) + tf32 GEMM + pool, layer 2 (K=128) ----------------
__global__ void __launch_bounds__(256, 3) k_gcn2(
    const float* __restrict__ W, const float* __restrict__ bias,
    const int* __restrict__ batch)
{
    constexpr int K = 128, KP = 132, BM = 64;
    __shared__ uint32_t sXu[BM * KP];

    int tid = threadIdx.x;
    int warp = tid >> 5, lane = tid & 31;
    int row0 = blockIdx.x * BM;

    // gather phase: warp per node, lane handles 4 halves (8B loads)
    for (int it = 0; it < 8; it++) {
        int nl = warp * 8 + it;
        int node = row0 + nl;
        float4 acc = make_float4(0.f, 0.f, 0.f, 0.f);
        if (node < NN) {
            acc = ldh4(&g_hws[node * EMB + lane * 4]);  // self
            int e = g_rowptr[node], end = g_rowptr[node + 1];
            for (; e + 4 <= end; e += 4) {
                int s0 = g_csr[e], s1 = g_csr[e + 1], s2 = g_csr[e + 2], s3 = g_csr[e + 3];
                float4 a0 = ldh4(&g_hws[s0 * EMB + lane * 4]);
                float4 a1 = ldh4(&g_hws[s1 * EMB + lane * 4]);
                float4 a2 = ldh4(&g_hws[s2 * EMB + lane * 4]);
                float4 a3 = ldh4(&g_hws[s3 * EMB + lane * 4]);
                acc = f4add(acc, f4add(f4add(a0, a1), f4add(a2, a3)));
            }
            for (; e < end; e++) {
                int s = g_csr[e];
                acc = f4add(acc, ldh4(&g_hws[s * EMB + lane * 4]));
            }
            float dn = g_dinv[node];
            acc.x *= dn; acc.y *= dn; acc.z *= dn; acc.w *= dn;
        }
        uint4 uv = make_uint4(cvt_tf32(acc.x), cvt_tf32(acc.y),
                              cvt_tf32(acc.z), cvt_tf32(acc.w));
        *(uint4*)&sXu[nl * KP + lane * 4] = uv;
    }
    __syncthreads();

    // tf32 GEMM
    int mt = warp & 3, nh = warp >> 2;
    int ra = lane >> 2, ca = lane & 3;
    float d[8][4];
#pragma unroll
    for (int nt = 0; nt < 8; nt++)
        d[nt][0] = d[nt][1] = d[nt][2] = d[nt][3] = 0.f;

#pragma unroll 4
    for (int k0 = 0; k0 < K; k0 += 8) {
        const uint32_t* pa = &sXu[(mt * 16 + ra) * KP + k0 + ca];
        uint32_t A[4] = { pa[0], pa[8 * KP], pa[4], pa[8 * KP + 4] };
        const float* wb = &W[(k0 + ca) * 128 + nh * 64 + ra];
#pragma unroll
        for (int nt = 0; nt < 8; nt++) {
            uint32_t b0 = cvt_tf32(__ldg(wb + nt * 8));
            uint32_t b1 = cvt_tf32(__ldg(wb + 4 * 128 + nt * 8));
            mma_tf32(d[nt], A, b0, b1);
        }
    }

    // epilogue: bias + relu + pooled red.add into g_gsum
    int gr0 = row0 + mt * 16 + ra;
    int gr1 = gr0 + 8;
    int b0i = (gr0 < NN) ? batch[gr0] : 0;
    int b1i = (gr1 < NN) ? batch[gr1] : 0;
#pragma unroll
    for (int nt = 0; nt < 8; nt++) {
        int col = nh * 64 + nt * 8 + 2 * ca;
        float bx = __ldg(&bias[col]), by = __ldg(&bias[col + 1]);
        if (gr0 < NN)
            red_add_v2(&g_gsum[b0i * EMB + col],
                       fmaxf(d[nt][0] + bx, 0.f), fmaxf(d[nt][1] + by, 0.f));
        if (gr1 < NN)
            red_add_v2(&g_gsum[b1i * EMB + col],
                       fmaxf(d[nt][2] + bx, 0.f), fmaxf(d[nt][3] + by, 0.f));
    }
}

// ---------------- fused bucketing ----------------
__global__ void __launch_bounds__(1024) k_bucket(const int* __restrict__ ecl) {
    __shared__ int s_cnt[NC];
    __shared__ int s_start[NC];
    __shared__ int s_cur[NC];
    int t = threadIdx.x;
    if (t < NC) s_cnt[t] = 0;
    __syncthreads();
    for (int p = t; p < NP; p += 1024) atomicAdd(&s_cnt[ecl[p]], 1);
    __syncthreads();
    if (t == 0) {
        int a = 0;
        for (int c = 0; c < NC; c++) {
            s_start[c] = a;
            a += ((s_cnt[c] + 31) / 32) * 32;
        }
    }
    __syncthreads();
    for (int i = t; i < BUCKET_SLOTS; i += 1024) g_bucket[i] = -1;
    if (t < NC) s_cur[t] = s_start[t];
    __syncthreads();
    for (int p = t; p < NP; p += 1024) {
        int c = ecl[p];
        int pos = atomicAdd(&s_cur[c], 1);
        g_bucket[pos] = p;
    }
}

// ---------------- tf32 tensor-core regressor: 32 pairs per block ----------------
// (mean normalization folded in: pair value = gsum[q]*ginv[q])
__global__ void __launch_bounds__(256) k_reg(
    const int* __restrict__ ddb, const int* __restrict__ ecl,
    const float* __restrict__ w1, const float* __restrict__ b1,
    const float* __restrict__ w2, const float* __restrict__ b2,
    float* __restrict__ out)
{
    __shared__ int      s_pid[32];
    __shared__ uint32_t s_pairU[32 * 268];
    __shared__ float    s_b1[HID];
    __shared__ float    s_w2[HID];
    __shared__ float    s_out[32];

    int tid = threadIdx.x;
    int warp = tid >> 5, lane = tid & 31;
    int base = blockIdx.x * 32;
    if (tid < 32) { s_pid[tid] = g_bucket[base + tid]; s_out[tid] = 0.f; }
    __syncthreads();

    int c = -1;
    for (int s = 0; s < 32 && c < 0; s++) {
        int p = s_pid[s];
        if (p >= 0) c = ecl[p];
    }
    if (c < 0) return;

    s_b1[tid] = b1[c * HID + tid];
    s_w2[tid] = w2[c * HID + tid];

    for (int i = tid; i < 32 * HID; i += 256) {
        int s = i >> 8, j = i & 255;
        int p = s_pid[s];
        float v = 0.0f;
        if (p >= 0) {
            int q = (j < 128) ? ddb[p] : ddb[NP + p];
            v = g_gsum[q * EMB + (j & 127)] * g_ginv[q];
        }
        s_pairU[s * 268 + j] = cvt_tf32(v);
    }
    __syncthreads();

    const float* Wc = w1 + c * (HID * HID);
    int n0 = warp * 32;
    int ra = lane >> 2, ca = lane & 3;

    float d[2][4][4];
#pragma unroll
    for (int mt = 0; mt < 2; mt++)
#pragma unroll
        for (int nt = 0; nt < 4; nt++)
            d[mt][nt][0] = d[mt][nt][1] = d[mt][nt][2] = d[mt][nt][3] = 0.f;

    for (int k0 = 0; k0 < HID; k0 += 8) {
        const uint32_t* pr = &s_pairU[ra * 268 + k0 + ca];
        uint32_t A[2][4];
        A[0][0] = pr[0];
        A[0][1] = pr[8 * 268];
        A[0][2] = pr[4];
        A[0][3] = pr[8 * 268 + 4];
        A[1][0] = pr[16 * 268];
        A[1][1] = pr[24 * 268];
        A[1][2] = pr[16 * 268 + 4];
        A[1][3] = pr[24 * 268 + 4];
        const float* wp0 = Wc + (k0 + ca) * HID + n0 + ra;
        const float* wp1 = wp0 + 4 * HID;
#pragma unroll
        for (int nt = 0; nt < 4; nt++) {
            uint32_t b0 = cvt_tf32(__ldg(wp0 + nt * 8));
            uint32_t b1v = cvt_tf32(__ldg(wp1 + nt * 8));
            mma_tf32(d[0][nt], A[0], b0, b1v);
            mma_tf32(d[1][nt], A[1], b0, b1v);
        }
    }

    float rowsum[2][2] = {{0.f, 0.f}, {0.f, 0.f}};
#pragma unroll
    for (int mt = 0; mt < 2; mt++) {
#pragma unroll
        for (int nt = 0; nt < 4; nt++) {
            int colb = n0 + nt * 8 + 2 * ca;
            float b1a = s_b1[colb],     w2a = s_w2[colb];
            float b1b = s_b1[colb + 1], w2b = s_w2[colb + 1];
            rowsum[mt][0] += fmaxf(d[mt][nt][0] + b1a, 0.f) * w2a
                           + fmaxf(d[mt][nt][1] + b1b, 0.f) * w2b;
            rowsum[mt][1] += fmaxf(d[mt][nt][2] + b1a, 0.f) * w2a
                           + fmaxf(d[mt][nt][3] + b1b, 0.f) * w2b;
        }
    }
#pragma unroll
    for (int mt = 0; mt < 2; mt++)
#pragma unroll
        for (int hi = 0; hi < 2; hi++) {
            float v = rowsum[mt][hi];
            v += __shfl_xor_sync(0xffffffffu, v, 1);
            v += __shfl_xor_sync(0xffffffffu, v, 2);
            if (ca == 0) atomicAdd(&s_out[mt * 16 + hi * 8 + ra], v);
        }
    __syncthreads();

    if (tid < 32) {
        int p = s_pid[tid];
        if (p >= 0) out[p] = s_out[tid] + b2[c];
    }
}

// ---------------- host launch ----------------
extern "C" void kernel_launch(void* const* d_in, const int* in_sizes, int n_in,
                              void* d_out, int out_size)
{
    const float* x    = (const float*)d_in[0];
    const float* c1w  = (const float*)d_in[1];
    const float* c1b  = (const float*)d_in[2];
    const float* c2w  = (const float*)d_in[3];
    const float* c2b  = (const float*)d_in[4];
    const float* rw1  = (const float*)d_in[5];
    const float* rb1  = (const float*)d_in[6];
    const float* rw2  = (const float*)d_in[7];
    const float* rb2  = (const float*)d_in[8];
    const int*   ei   = (const int*)d_in[9];
    const int*   bat  = (const int*)d_in[10];
    const int*   ddb  = (const int*)d_in[11];
    const int*   ecl  = (const int*)d_in[12];
    float* out = (float*)d_out;

    // side stream + events (created once; host resources, no device allocation)
    static cudaStream_t s1 = nullptr;
    static cudaEvent_t evFork = nullptr, evJoin = nullptr;
    if (s1 == nullptr) {
        cudaStreamCreateWithFlags(&s1, cudaStreamNonBlocking);
        cudaEventCreateWithFlags(&evFork, cudaEventDisableTiming);
        cudaEventCreateWithFlags(&evJoin, cudaEventDisableTiming);
    }

    void* icnt_ptr = nullptr;
    void* gsum_ptr = nullptr;
    cudaGetSymbolAddress(&icnt_ptr, g_icnt);
    cudaGetSymbolAddress(&gsum_ptr, g_gsum);

    const int T = 256;

    // fork: side branch runs work independent of the CSR chain
    cudaEventRecord(evFork, 0);
    cudaStreamWaitEvent(s1, evFork, 0);
    cudaMemsetAsync(gsum_ptr, 0, NG * EMB * sizeof(float), s1);
    k_tohalf<<<(NN * INCH / 4 + T - 1) / T, T, 0, s1>>>(x);
    k_cntg<<<(NG + T - 1) / T, T, 0, s1>>>(bat);
    k_bucket<<<1, 1024, 0, s1>>>(ecl);
    cudaEventRecord(evJoin, s1);

    // main branch: CSR build chain
    cudaMemsetAsync(icnt_ptr, 0, NN * sizeof(int), 0);
    k_icnt<<<(NE / 8 + T - 1) / T, T>>>(ei);
    k_scan1<<<NBLK, NPB>>>();
    k_scan2<<<1, 512>>>();
    k_scan3<<<NBLK, NPB>>>();
    k_fill<<<(NE / 4 + T - 1) / T, T>>>(ei);

    // join before the consumers of the side branch
    cudaStreamWaitEvent(0, evJoin, 0);

    // layer 1 + layer 2 + regressor (mean folded into k_reg)
    k_gcn1<<<(NN + 63) / 64, T>>>(c1w, c1b);
    k_gcn2<<<(NN + 63) / 64, T>>>(c2w, c2b, bat);
    k_reg<<<REG_BLOCKS, T>>>(ddb, ecl, rw1, rb1, rw2, rb2, out);
}

// round 15
// speedup vs baseline: 1.6076x; 1.0335x over previous
#include <cuda_runtime.h>
#include <cuda_fp16.h>
#include <math.h>
#include <stdint.h>

#define NN 50000
#define NE 800000
#define NG 1024
#define NP 16384
#define NC 16
#define INCH 64
#define EMB 128
#define HID 256
#define BUCKET_SLOTS ((NP / 32 + NC) * 32)   // 16896
#define REG_BLOCKS (NP / 32 + NC)            // 528
#define NPB 128
#define NBLK ((NN + NPB - 1) / NPB)           // 391

// ---------------- scratch (static zero-init at context load) ----------------
__device__ float  g_dinv[NN];
__device__ int    g_icnt[NN];        // zeroed statically; re-zeroed by k_fill each run
__device__ int    g_rowptr[NN + 1];
__device__ int    g_rank[NE];
__device__ int    g_bsum[512];
__device__ int    g_csr[NE];
__device__ __half g_xh[NN * INCH];
__device__ __half g_hws[NN * EMB];
__device__ float  g_gsum[NG * EMB];  // zeroed by k_side each run
__device__ float  g_ginv[NG];
__device__ int    g_bucket[BUCKET_SLOTS];

// ---------------- helpers ----------------
__device__ __forceinline__ void red_add_v2(float* addr, float a, float b) {
    asm volatile("red.global.add.v2.f32 [%0], {%1, %2};"
                 :: "l"(addr), "f"(a), "f"(b) : "memory");
}
__device__ __forceinline__ float4 f4add(float4 a, float4 b) {
    return make_float4(a.x + b.x, a.y + b.y, a.z + b.z, a.w + b.w);
}
__device__ __forceinline__ uint32_t cvt_tf32(float f) {
    uint32_t u;
    asm("cvt.rna.tf32.f32 %0, %1;" : "=r"(u) : "f"(f));
    return u;
}
__device__ __forceinline__ void mma_tf32(float* d, const uint32_t* a,
                                         uint32_t b0, uint32_t b1) {
    asm("mma.sync.aligned.m16n8k8.row.col.f32.tf32.tf32.f32 "
        "{%0,%1,%2,%3}, {%4,%5,%6,%7}, {%8,%9}, {%0,%1,%2,%3};"
        : "+f"(d[0]), "+f"(d[1]), "+f"(d[2]), "+f"(d[3])
        : "r"(a[0]), "r"(a[1]), "r"(a[2]), "r"(a[3]), "r"(b0), "r"(b1));
}
__device__ __forceinline__ float4 ldh4(const __half* p) {
    uint2 u = *(const uint2*)p;
    __half2 h0 = *(__half2*)&u.x, h1 = *(__half2*)&u.y;
    float2 f0 = __half22float2(h0), f1 = __half22float2(h1);
    return make_float4(f0.x, f0.y, f1.x, f1.y);
}

// ---------------- degree histogram + per-edge rank (4 edges per thread) ----------------
__global__ void k_icnt(const int* __restrict__ ei) {
    int i = blockIdx.x * blockDim.x + threadIdx.x;
    if (i < NE / 4) {
        int4 t = ((const int4*)(ei + NE))[i];
        int4 k;
        k.x = atomicAdd(&g_icnt[t.x], 1);
        k.y = atomicAdd(&g_icnt[t.y], 1);
        k.z = atomicAdd(&g_icnt[t.z], 1);
        k.w = atomicAdd(&g_icnt[t.w], 1);
        ((int4*)g_rank)[i] = k;
    }
}

// ---------------- scan stage 1: per-block sums (+ fused dinv) ----------------
__global__ void k_scan1() {
    __shared__ int sm[NPB];
    int i = blockIdx.x * NPB + threadIdx.x;
    int v = (i < NN) ? g_icnt[i] : 0;
    if (i < NN) g_dinv[i] = rsqrtf((float)(v + 1));
    sm[threadIdx.x] = v;
    __syncthreads();
    for (int s = NPB / 2; s > 0; s >>= 1) {
        if (threadIdx.x < s) sm[threadIdx.x] += sm[threadIdx.x + s];
        __syncthreads();
    }
    if (threadIdx.x == 0) g_bsum[blockIdx.x] = sm[0];
}
// ---------------- scan stage 2 (fused): block-prefix + local scan -> rowptr ----------------
__global__ void k_scan3() {
    __shared__ int red[NPB];
    __shared__ int sm[NPB];
    int t = threadIdx.x, bid = blockIdx.x;

    // exclusive prefix over block sums (each block sums bsum[0..bid))
    int ps = 0;
    for (int j = t; j < bid; j += NPB) ps += g_bsum[j];
    red[t] = ps;
    __syncthreads();
    for (int s = NPB / 2; s > 0; s >>= 1) {
        if (t < s) red[t] += red[t + s];
        __syncthreads();
    }
    int base = red[0];

    // local inclusive scan
    int i = bid * NPB + t;
    int v = (i < NN) ? g_icnt[i] : 0;
    sm[t] = v;
    __syncthreads();
    for (int s = 1; s < NPB; s <<= 1) {
        int a = (t >= s) ? sm[t - s] : 0;
        __syncthreads();
        sm[t] += a;
        __syncthreads();
    }
    if (i < NN) {
        g_rowptr[i] = base + sm[t] - v;
        if (i == NN - 1) g_rowptr[NN] = NE;
    }
}

// ---------------- fill without atomics + re-zero g_icnt for next run ----------------
__global__ void k_fill(const int* __restrict__ ei) {
    int i = blockIdx.x * blockDim.x + threadIdx.x;
    if (i < NE / 4) {
        int4 c = ((const int4*)(ei + NE))[i];
        int4 r = ((const int4*)ei)[i];
        int4 k = ((const int4*)g_rank)[i];
        g_csr[g_rowptr[c.x] + k.x] = r.x;
        g_csr[g_rowptr[c.y] + k.y] = r.y;
        g_csr[g_rowptr[c.z] + k.z] = r.z;
        g_csr[g_rowptr[c.w] + k.w] = r.w;
    }
    if (i < NN / 4)   // NN divisible by 4; scan3 (last reader of icnt) already done
        ((int4*)g_icnt)[i] = make_int4(0, 0, 0, 0);
}

// ---------------- fused side kernel: tohalf | gsum-zero + cntg | bucket ----------------
#define SIDE_TOHALF_BLOCKS ((NN * INCH / 4 + 1023) / 1024)   // 782
#define SIDE_GSUM_BLOCKS   (NG * EMB / 4 / 1024)             // 32
#define SIDE_BLOCKS        (SIDE_TOHALF_BLOCKS + SIDE_GSUM_BLOCKS + 1)
__global__ void __launch_bounds__(1024) k_side(
    const float* __restrict__ x, const int* __restrict__ batch,
    const int* __restrict__ ecl)
{
    int b = blockIdx.x;
    int t = threadIdx.x;
    if (b < SIDE_TOHALF_BLOCKS) {
        int i = b * 1024 + t;
        if (i < NN * INCH / 4) {
            float4 v = ((const float4*)x)[i];
            __half2 h0 = __floats2half2_rn(v.x, v.y);
            __half2 h1 = __floats2half2_rn(v.z, v.w);
            ((uint2*)g_xh)[i] = make_uint2(*(uint32_t*)&h0, *(uint32_t*)&h1);
        }
        return;
    }
    if (b < SIDE_TOHALF_BLOCKS + SIDE_GSUM_BLOCKS) {
        int i = (b - SIDE_TOHALF_BLOCKS) * 1024 + t;
        ((float4*)g_gsum)[i] = make_float4(0.f, 0.f, 0.f, 0.f);  // exactly 32768 float4
        if (i < NG) {   // per-graph 1/cnt via binary search (batch sorted)
            int g = i;
            int lo = 0, hi = NN;
            while (lo < hi) { int m = (lo + hi) >> 1; if (batch[m] < g) lo = m + 1; else hi = m; }
            int a = lo;
            hi = NN;
            while (lo < hi) { int m = (lo + hi) >> 1; if (batch[m] < g + 1) lo = m + 1; else hi = m; }
            g_ginv[g] = 1.0f / fmaxf((float)(lo - a), 1.0f);
        }
        return;
    }
    // bucket block (single block of 1024)
    __shared__ int s_cnt[NC];
    __shared__ int s_start[NC];
    __shared__ int s_cur[NC];
    if (t < NC) s_cnt[t] = 0;
    __syncthreads();
    for (int p = t; p < NP; p += 1024) atomicAdd(&s_cnt[ecl[p]], 1);
    __syncthreads();
    if (t == 0) {
        int a = 0;
        for (int c = 0; c < NC; c++) {
            s_start[c] = a;
            a += ((s_cnt[c] + 31) / 32) * 32;
        }
    }
    __syncthreads();
    for (int i = t; i < BUCKET_SLOTS; i += 1024) g_bucket[i] = -1;
    if (t < NC) s_cur[t] = s_start[t];
    __syncthreads();
    for (int p = t; p < NP; p += 1024) {
        int c = ecl[p];
        int pos = atomicAdd(&s_cur[c], 1);
        g_bucket[pos] = p;
    }
}

// ---------------- fused gather(fp16) + tf32 GEMM, layer 1 (K=64) ----------------
__global__ void __launch_bounds__(256, 3) k_gcn1(
    const float* __restrict__ W, const float* __restrict__ bias)
{
    constexpr int K = 64, KP = 68, BM = 64;
    __shared__ uint32_t sXu[BM * KP];

    int tid = threadIdx.x;
    int warp = tid >> 5, lane = tid & 31;
    int row0 = blockIdx.x * BM;

    int half = lane >> 4, l = lane & 15;
    for (int it = 0; it < 4; it++) {
        int nl = warp * 8 + it * 2 + half;
        int node = row0 + nl;
        float4 acc = make_float4(0.f, 0.f, 0.f, 0.f);
        if (node < NN) {
            float dn = g_dinv[node];
            acc = ldh4(&g_xh[node * INCH + l * 4]);
            acc.x *= dn; acc.y *= dn; acc.z *= dn; acc.w *= dn;
            int e = g_rowptr[node], end = g_rowptr[node + 1];
            for (; e + 4 <= end; e += 4) {
                int s0 = g_csr[e], s1 = g_csr[e + 1], s2 = g_csr[e + 2], s3 = g_csr[e + 3];
                float4 a0 = ldh4(&g_xh[s0 * INCH + l * 4]);
                float4 a1 = ldh4(&g_xh[s1 * INCH + l * 4]);
                float4 a2 = ldh4(&g_xh[s2 * INCH + l * 4]);
                float4 a3 = ldh4(&g_xh[s3 * INCH + l * 4]);
                float d0 = g_dinv[s0], d1 = g_dinv[s1], d2 = g_dinv[s2], d3 = g_dinv[s3];
                acc.x = fmaf(d0, a0.x, fmaf(d1, a1.x, fmaf(d2, a2.x, fmaf(d3, a3.x, acc.x))));
                acc.y = fmaf(d0, a0.y, fmaf(d1, a1.y, fmaf(d2, a2.y, fmaf(d3, a3.y, acc.y))));
                acc.z = fmaf(d0, a0.z, fmaf(d1, a1.z, fmaf(d2, a2.z, fmaf(d3, a3.z, acc.z))));
                acc.w = fmaf(d0, a0.w, fmaf(d1, a1.w, fmaf(d2, a2.w, fmaf(d3, a3.w, acc.w))));
            }
            for (; e < end; e++) {
                int s = g_csr[e];
                float4 a = ldh4(&g_xh[s * INCH + l * 4]);
                float ds = g_dinv[s];
                acc.x = fmaf(ds, a.x, acc.x);
                acc.y = fmaf(ds, a.y, acc.y);
                acc.z = fmaf(ds, a.z, acc.z);
                acc.w = fmaf(ds, a.w, acc.w);
            }
            acc.x *= dn; acc.y *= dn; acc.z *= dn; acc.w *= dn;  // left norm
        }
        uint4 uv = make_uint4(cvt_tf32(acc.x), cvt_tf32(acc.y),
                              cvt_tf32(acc.z), cvt_tf32(acc.w));
        *(uint4*)&sXu[nl * KP + l * 4] = uv;
    }
    __syncthreads();

    int mt = warp & 3, nh = warp >> 2;
    int ra = lane >> 2, ca = lane & 3;
    float d[8][4];
#pragma unroll
    for (int nt = 0; nt < 8; nt++)
        d[nt][0] = d[nt][1] = d[nt][2] = d[nt][3] = 0.f;

#pragma unroll
    for (int k0 = 0; k0 < K; k0 += 8) {
        const uint32_t* pa = &sXu[(mt * 16 + ra) * KP + k0 + ca];
        uint32_t A[4] = { pa[0], pa[8 * KP], pa[4], pa[8 * KP + 4] };
        const float* wb = &W[(k0 + ca) * 128 + nh * 64 + ra];
#pragma unroll
        for (int nt = 0; nt < 8; nt++) {
            uint32_t b0 = cvt_tf32(__ldg(wb + nt * 8));
            uint32_t b1 = cvt_tf32(__ldg(wb + 4 * 128 + nt * 8));
            mma_tf32(d[nt], A, b0, b1);
        }
    }

    int gr0 = row0 + mt * 16 + ra;
    int gr1 = gr0 + 8;
    float dv0 = (gr0 < NN) ? g_dinv[gr0] : 0.f;
    float dv1 = (gr1 < NN) ? g_dinv[gr1] : 0.f;
#pragma unroll
    for (int nt = 0; nt < 8; nt++) {
        int col = nh * 64 + nt * 8 + 2 * ca;
        float bx = __ldg(&bias[col]), by = __ldg(&bias[col + 1]);
        if (gr0 < NN) {
            __half2 o = __floats2half2_rn(fmaxf(d[nt][0] + bx, 0.f) * dv0,
                                          fmaxf(d[nt][1] + by, 0.f) * dv0);
            *(__half2*)&g_hws[gr0 * EMB + col] = o;
        }
        if (gr1 < NN) {
            __half2 o = __floats2half2_rn(fmaxf(d[nt][2] + bx, 0.f) * dv1,
                                          fmaxf(d[nt][3] + by, 0.f) * dv1);
            *(__half2*)&g_hws[gr1 * EMB + col] = o;
        }
    }
}

// ---------------- fused gather(fp16) + tf32 GEMM + pool, layer 2 (K=128) ----------------
__global__ void __launch_bounds__(256, 3) k_gcn2(
    const float* __restrict__ W, const float* __restrict__ bias,
    const int* __restrict__ batch)
{
    constexpr int K = 128, KP = 132, BM = 64;
    __shared__ uint32_t sXu[BM * KP];

    int tid = threadIdx.x;
    int warp = tid >> 5, lane = tid & 31;
    int row0 = blockIdx.x * BM;

    for (int it = 0; it < 8; it++) {
        int nl = warp * 8 + it;
        int node = row0 + nl;
        float4 acc = make_float4(0.f, 0.f, 0.f, 0.f);
        if (node < NN) {
            acc = ldh4(&g_hws[node * EMB + lane * 4]);  // self
            int e = g_rowptr[node], end = g_rowptr[node + 1];
            for (; e + 4 <= end; e += 4) {
                int s0 = g_csr[e], s1 = g_csr[e + 1], s2 = g_csr[e + 2], s3 = g_csr[e + 3];
                float4 a0 = ldh4(&g_hws[s0 * EMB + lane * 4]);
                float4 a1 = ldh4(&g_hws[s1 * EMB + lane * 4]);
                float4 a2 = ldh4(&g_hws[s2 * EMB + lane * 4]);
                float4 a3 = ldh4(&g_hws[s3 * EMB + lane * 4]);
                acc = f4add(acc, f4add(f4add(a0, a1), f4add(a2, a3)));
            }
            for (; e < end; e++) {
                int s = g_csr[e];
                acc = f4add(acc, ldh4(&g_hws[s * EMB + lane * 4]));
            }
            float dn = g_dinv[node];
            acc.x *= dn; acc.y *= dn; acc.z *= dn; acc.w *= dn;
        }
        uint4 uv = make_uint4(cvt_tf32(acc.x), cvt_tf32(acc.y),
                              cvt_tf32(acc.z), cvt_tf32(acc.w));
        *(uint4*)&sXu[nl * KP + lane * 4] = uv;
    }
    __syncthreads();

    int mt = warp & 3, nh = warp >> 2;
    int ra = lane >> 2, ca = lane & 3;
    float d[8][4];
#pragma unroll
    for (int nt = 0; nt < 8; nt++)
        d[nt][0] = d[nt][1] = d[nt][2] = d[nt][3] = 0.f;

#pragma unroll 4
    for (int k0 = 0; k0 < K; k0 += 8) {
        const uint32_t* pa = &sXu[(mt * 16 + ra) * KP + k0 + ca];
        uint32_t A[4] = { pa[0], pa[8 * KP], pa[4], pa[8 * KP + 4] };
        const float* wb = &W[(k0 + ca) * 128 + nh * 64 + ra];
#pragma unroll
        for (int nt = 0; nt < 8; nt++) {
            uint32_t b0 = cvt_tf32(__ldg(wb + nt * 8));
            uint32_t b1 = cvt_tf32(__ldg(wb + 4 * 128 + nt * 8));
            mma_tf32(d[nt], A, b0, b1);
        }
    }

    int gr0 = row0 + mt * 16 + ra;
    int gr1 = gr0 + 8;
    int b0i = (gr0 < NN) ? batch[gr0] : 0;
    int b1i = (gr1 < NN) ? batch[gr1] : 0;
#pragma unroll
    for (int nt = 0; nt < 8; nt++) {
        int col = nh * 64 + nt * 8 + 2 * ca;
        float bx = __ldg(&bias[col]), by = __ldg(&bias[col + 1]);
        if (gr0 < NN)
            red_add_v2(&g_gsum[b0i * EMB + col],
                       fmaxf(d[nt][0] + bx, 0.f), fmaxf(d[nt][1] + by, 0.f));
        if (gr1 < NN)
            red_add_v2(&g_gsum[b1i * EMB + col],
                       fmaxf(d[nt][2] + bx, 0.f), fmaxf(d[nt][3] + by, 0.f));
    }
}

// ---------------- tf32 tensor-core regressor: 32 pairs per block ----------------
__global__ void __launch_bounds__(256) k_reg(
    const int* __restrict__ ddb, const int* __restrict__ ecl,
    const float* __restrict__ w1, const float* __restrict__ b1,
    const float* __restrict__ w2, const float* __restrict__ b2,
    float* __restrict__ out)
{
    __shared__ int      s_pid[32];
    __shared__ uint32_t s_pairU[32 * 268];
    __shared__ float    s_b1[HID];
    __shared__ float    s_w2[HID];
    __shared__ float    s_out[32];

    int tid = threadIdx.x;
    int warp = tid >> 5, lane = tid & 31;
    int base = blockIdx.x * 32;
    if (tid < 32) { s_pid[tid] = g_bucket[base + tid]; s_out[tid] = 0.f; }
    __syncthreads();

    int c = -1;
    for (int s = 0; s < 32 && c < 0; s++) {
        int p = s_pid[s];
        if (p >= 0) c = ecl[p];
    }
    if (c < 0) return;

    s_b1[tid] = b1[c * HID + tid];
    s_w2[tid] = w2[c * HID + tid];

    for (int i = tid; i < 32 * HID; i += 256) {
        int s = i >> 8, j = i & 255;
        int p = s_pid[s];
        float v = 0.0f;
        if (p >= 0) {
            int q = (j < 128) ? ddb[p] : ddb[NP + p];
            v = g_gsum[q * EMB + (j & 127)] * g_ginv[q];
        }
        s_pairU[s * 268 + j] = cvt_tf32(v);
    }
    __syncthreads();

    const float* Wc = w1 + c * (HID * HID);
    int n0 = warp * 32;
    int ra = lane >> 2, ca = lane & 3;

    float d[2][4][4];
#pragma unroll
    for (int mt = 0; mt < 2; mt++)
#pragma unroll
        for (int nt = 0; nt < 4; nt++)
            d[mt][nt][0] = d[mt][nt][1] = d[mt][nt][2] = d[mt][nt][3] = 0.f;

    for (int k0 = 0; k0 < HID; k0 += 8) {
        const uint32_t* pr = &s_pairU[ra * 268 + k0 + ca];
        uint32_t A[2][4];
        A[0][0] = pr[0];
        A[0][1] = pr[8 * 268];
        A[0][2] = pr[4];
        A[0][3] = pr[8 * 268 + 4];
        A[1][0] = pr[16 * 268];
        A[1][1] = pr[24 * 268];
        A[1][2] = pr[16 * 268 + 4];
        A[1][3] = pr[24 * 268 + 4];
        const float* wp0 = Wc + (k0 + ca) * HID + n0 + ra;
        const float* wp1 = wp0 + 4 * HID;
#pragma unroll
        for (int nt = 0; nt < 4; nt++) {
            uint32_t b0 = cvt_tf32(__ldg(wp0 + nt * 8));
            uint32_t b1v = cvt_tf32(__ldg(wp1 + nt * 8));
            mma_tf32(d[0][nt], A[0], b0, b1v);
            mma_tf32(d[1][nt], A[1], b0, b1v);
        }
    }

    float rowsum[2][2] = {{0.f, 0.f}, {0.f, 0.f}};
#pragma unroll
    for (int mt = 0; mt < 2; mt++) {
#pragma unroll
        for (int nt = 0; nt < 4; nt++) {
            int colb = n0 + nt * 8 + 2 * ca;
            float b1a = s_b1[colb],     w2a = s_w2[colb];
            float b1b = s_b1[colb + 1], w2b = s_w2[colb + 1];
            rowsum[mt][0] += fmaxf(d[mt][nt][0] + b1a, 0.f) * w2a
                           + fmaxf(d[mt][nt][1] + b1b, 0.f) * w2b;
            rowsum[mt][1] += fmaxf(d[mt][nt][2] + b1a, 0.f) * w2a
                           + fmaxf(d[mt][nt][3] + b1b, 0.f) * w2b;
        }
    }
#pragma unroll
    for (int mt = 0; mt < 2; mt++)
#pragma unroll
        for (int hi = 0; hi < 2; hi++) {
            float v = rowsum[mt][hi];
            v += __shfl_xor_sync(0xffffffffu, v, 1);
            v += __shfl_xor_sync(0xffffffffu, v, 2);
            if (ca == 0) atomicAdd(&s_out[mt * 16 + hi * 8 + ra], v);
        }
    __syncthreads();

    if (tid < 32) {
        int p = s_pid[tid];
        if (p >= 0) out[p] = s_out[tid] + b2[c];
    }
}

// ---------------- host launch ----------------
extern "C" void kernel_launch(void* const* d_in, const int* in_sizes, int n_in,
                              void* d_out, int out_size)
{
    const float* x    = (const float*)d_in[0];
    const float* c1w  = (const float*)d_in[1];
    const float* c1b  = (const float*)d_in[2];
    const float* c2w  = (const float*)d_in[3];
    const float* c2b  = (const float*)d_in[4];
    const float* rw1  = (const float*)d_in[5];
    const float* rb1  = (const float*)d_in[6];
    const float* rw2  = (const float*)d_in[7];
    const float* rb2  = (const float*)d_in[8];
    const int*   ei   = (const int*)d_in[9];
    const int*   bat  = (const int*)d_in[10];
    const int*   ddb  = (const int*)d_in[11];
    const int*   ecl  = (const int*)d_in[12];
    float* out = (float*)d_out;

    static cudaStream_t s1 = nullptr;
    static cudaEvent_t evFork = nullptr, evJoin = nullptr;
    if (s1 == nullptr) {
        cudaStreamCreateWithFlags(&s1, cudaStreamNonBlocking);
        cudaEventCreateWithFlags(&evFork, cudaEventDisableTiming);
        cudaEventCreateWithFlags(&evJoin, cudaEventDisableTiming);
    }

    const int T = 256;

    // fork point (before main chain; side branch depends on nothing prior)
    cudaEventRecord(evFork, 0);

    // main branch: CSR build chain (g_icnt is zero: static init + k_fill restore)
    k_icnt<<<(NE / 4 + T - 1) / T, T>>>(ei);        // launch 1
    k_scan1<<<NBLK, NPB>>>();                        // launch 2
    k_scan3<<<NBLK, NPB>>>();                        // launch 3 (block-prefix fused)
    k_fill<<<(NE / 4 + T - 1) / T, T>>>(ei);         // launch 4 (+ re-zero icnt)

    // side branch: tohalf | gsum-zero + cntg | bucket (one kernel)
    cudaStreamWaitEvent(s1, evFork, 0);
    k_side<<<SIDE_BLOCKS, 1024, 0, s1>>>(x, bat, ecl);   // launch 5
    cudaEventRecord(evJoin, s1);
    cudaStreamWaitEvent(0, evJoin, 0);

    // layers + regressor
    k_gcn1<<<(NN + 63) / 64, T>>>(c1w, c1b);         // launch 6 (profiled by ncu -s 5)
    k_gcn2<<<(NN + 63) / 64, T>>>(c2w, c2b, bat);    // launch 7
    k_reg<<<REG_BLOCKS, T>>>(ddb, ecl, rw1, rb1, rw2, rb2, out);   // launch 8
}